// round 13
// baseline (speedup 1.0000x reference)
#include <cuda_runtime.h>

#define NTX 100000
#define NUS 50000
#define NEG 500000

typedef unsigned long long u64t;

// ---------------- scratch (static device globals; no allocation) ----------------
__device__ float g_h_tx[NTX * 64];
__device__ float g_h_us[NUS * 64];
__device__ float g_hs_u2t[NUS * 256];  // transform-first source features (u2t)
__device__ float g_agg_u[NUS * 256];
__device__ float g_t1[NTX * 256];
__device__ float g_u1[NUS * 256];
__device__ float g_hs2[NUS * 32];
__device__ float g_als_u2t[NUS * 4];
__device__ float g_ald_u2t[NTX * 4];
__device__ float g_als_t2u[NTX * 4];
__device__ float g_ald_t2u[NUS * 4];
__device__ float g_als2[NUS];
__device__ float g_ald2[NTX];
__device__ float g_vas_u2t[256];
__device__ float g_vad_u2t[256];
__device__ float g_vas_t2u[256];
__device__ float g_vad_t2u[256];
__device__ float g_vad2[256];
__device__ int g_deg_t[NTX], g_off_t[NTX], g_cnt_t[NTX];
__device__ int g_deg_u[NUS], g_off_u[NUS], g_cnt_u[NUS];
__device__ int g_csr_t[NEG], g_csr_u[NEG];
__device__ int g_sums_t[1024], g_sums_u[1024];

// ---------------- helpers ----------------
__device__ __forceinline__ float warp_sum(float v) {
    #pragma unroll
    for (int o = 16; o; o >>= 1) v += __shfl_xor_sync(0xffffffffu, v, o);
    return v;
}
__device__ __forceinline__ float lrelu(float x) { return x > 0.f ? x : 0.2f * x; }
__device__ __forceinline__ float elu(float x)   { return x > 0.f ? x : expm1f(x); }
__device__ __forceinline__ u64t pack2(float x) {
    u64t r;
    unsigned u = __float_as_uint(x);
    asm("mov.b64 %0, {%1, %1};" : "=l"(r) : "r"(u));
    return r;
}

// ---------------- CSR build (merged both directions) ----------------
__global__ void kzero(int* __restrict__ a, int na, int* __restrict__ b, int nb,
                      int* __restrict__ c, int nc, int* __restrict__ d, int nd) {
    int i = blockIdx.x * blockDim.x + threadIdx.x;
    if (i < na) a[i] = 0;
    if (i < nb) b[i] = 0;
    if (i < nc) c[i] = 0;
    if (i < nd) d[i] = 0;
}
__global__ void khist2(const int* __restrict__ ei_u2t, const int* __restrict__ ei_t2u,
                       int* __restrict__ deg_t, int* __restrict__ deg_u, int E) {
    int i = blockIdx.x * blockDim.x + threadIdx.x;
    if (i < E)               atomicAdd(&deg_t[ei_u2t[E + i]], 1);
    else if (i < 2 * E)      atomicAdd(&deg_u[ei_t2u[E + (i - E)]], 1);
}
__global__ void kscan1m(const int* __restrict__ in_t, int* __restrict__ out_t,
                        int* __restrict__ sums_t, int nt,
                        const int* __restrict__ in_u, int* __restrict__ out_u,
                        int* __restrict__ sums_u, int nu, int nbt) {
    __shared__ int sh[1024];
    const int* in; int* out; int* sums; int n; int b;
    if (blockIdx.x < nbt) { in = in_t; out = out_t; sums = sums_t; n = nt; b = blockIdx.x; }
    else                  { in = in_u; out = out_u; sums = sums_u; n = nu; b = blockIdx.x - nbt; }
    int i = b * 1024 + threadIdx.x;
    int v = (i < n) ? in[i] : 0;
    sh[threadIdx.x] = v;
    __syncthreads();
    for (int s = 1; s < 1024; s <<= 1) {
        int t = (threadIdx.x >= s) ? sh[threadIdx.x - s] : 0;
        __syncthreads();
        sh[threadIdx.x] += t;
        __syncthreads();
    }
    if (i < n) out[i] = sh[threadIdx.x] - v;
    if (threadIdx.x == 1023) sums[b] = sh[1023];
}
__global__ void kscan2m(int* __restrict__ sums_t, int nbt,
                        int* __restrict__ sums_u, int nbu) {
    __shared__ int sh[1024];
    int* sums = (blockIdx.x == 0) ? sums_t : sums_u;
    int nb = (blockIdx.x == 0) ? nbt : nbu;
    int v = (threadIdx.x < nb) ? sums[threadIdx.x] : 0;
    sh[threadIdx.x] = v;
    __syncthreads();
    for (int s = 1; s < 1024; s <<= 1) {
        int t = (threadIdx.x >= s) ? sh[threadIdx.x - s] : 0;
        __syncthreads();
        sh[threadIdx.x] += t;
        __syncthreads();
    }
    if (threadIdx.x < nb) sums[threadIdx.x] = sh[threadIdx.x] - v;
}
__global__ void kscan3m(int* __restrict__ out_t, const int* __restrict__ sums_t, int nt,
                        int* __restrict__ out_u, const int* __restrict__ sums_u, int nu,
                        int nbt) {
    int* out; const int* sums; int n; int b;
    if (blockIdx.x < nbt) { out = out_t; sums = sums_t; n = nt; b = blockIdx.x; }
    else                  { out = out_u; sums = sums_u; n = nu; b = blockIdx.x - nbt; }
    int i = b * 1024 + threadIdx.x;
    if (i < n) out[i] += sums[b];
}
__global__ void kscatter2(const int* __restrict__ ei_u2t, const int* __restrict__ ei_t2u,
                          const int* __restrict__ off_t, int* __restrict__ cnt_t,
                          int* __restrict__ csr_t,
                          const int* __restrict__ off_u, int* __restrict__ cnt_u,
                          int* __restrict__ csr_u, int E) {
    int i = blockIdx.x * blockDim.x + threadIdx.x;
    if (i < E) {
        int d = ei_u2t[E + i];
        int p = atomicAdd(&cnt_t[d], 1);
        csr_t[off_t[d] + p] = ei_u2t[i];
    } else if (i < 2 * E) {
        int j = i - E;
        int d = ei_t2u[E + j];
        int p = atomicAdd(&cnt_u[d], 1);
        csr_u[off_u[d] + p] = ei_t2u[j];
    }
}

// ---------------- FFMA2 SGEMM core ----------------
#define APHYS(m) ((m) + (((m) >> 4) << 1))
#define BPHYS(c) ((c) + ((((c) >> 5) & 1) << 2))

__device__ __forceinline__ void gemm_body(
    const float* __restrict__ A, const float* __restrict__ B,
    const float* __restrict__ bias, float* __restrict__ C,
    int M, int N, int K, int lda, int ldb, int ldc, int act, int bm,
    float (&At)[2][16][288], float (&Bs)[2][16][68]) {
    const int tid = threadIdx.x;
    const int tr = tid >> 3;
    const int tc = tid & 7;
    const int brow = tid >> 4;
    const int bcolL = (tid & 15) * 4;
    const int bcol = tc * 8;
    const int abase2 = tr * 4 + (tr >> 1);
    const int bbL = BPHYS(bcolL);
    const int bb = BPHYS(bcol);

    u64t c2[4][8];
    #pragma unroll
    for (int i = 0; i < 4; i++)
        #pragma unroll
        for (int j = 0; j < 8; j++) c2[i][j] = 0ull;

    const int r0 = bm + tid;
    const bool v0ok = r0 < M;
    const float* A0 = v0ok ? (A + (size_t)r0 * lda) : A;
    const int p0 = APHYS(tid);
    const int NK = K >> 4;

    {
        #pragma unroll
        for (int q = 0; q < 4; q++) {
            float4 a0 = v0ok ? *(const float4*)(A0 + q * 4) : make_float4(0.f, 0.f, 0.f, 0.f);
            At[0][q * 4 + 0][p0] = a0.x; At[0][q * 4 + 1][p0] = a0.y;
            At[0][q * 4 + 2][p0] = a0.z; At[0][q * 4 + 3][p0] = a0.w;
        }
        float4 w = (bcolL < N) ? *(const float4*)(B + (size_t)brow * ldb + bcolL)
                               : make_float4(0.f, 0.f, 0.f, 0.f);
        *(float4*)&Bs[0][brow][bbL] = w;
    }
    __syncthreads();

    for (int t = 0; t < NK; t++) {
        const int cur = t & 1, nxt = cur ^ 1;
        float4 na[4], nw;
        bool havenext = (t + 1 < NK);
        if (havenext) {
            const int k0 = (t + 1) << 4;
            #pragma unroll
            for (int q = 0; q < 4; q++)
                na[q] = v0ok ? *(const float4*)(A0 + k0 + q * 4) : make_float4(0.f, 0.f, 0.f, 0.f);
            nw = (bcolL < N) ? *(const float4*)(B + (size_t)(k0 + brow) * ldb + bcolL)
                             : make_float4(0.f, 0.f, 0.f, 0.f);
        }
        #pragma unroll
        for (int k = 0; k < 16; k++) {
            u64t a2[4];
            const u64t* Ap = (const u64t*)&At[cur][k][0];
            #pragma unroll
            for (int i = 0; i < 4; i++) a2[i] = Ap[abase2 + i];
            float4 w0 = *(const float4*)&Bs[cur][k][bb];
            float4 w1 = *(const float4*)&Bs[cur][k][bb + 4];
            u64t b2[8];
            b2[0] = pack2(w0.x); b2[1] = pack2(w0.y); b2[2] = pack2(w0.z); b2[3] = pack2(w0.w);
            b2[4] = pack2(w1.x); b2[5] = pack2(w1.y); b2[6] = pack2(w1.z); b2[7] = pack2(w1.w);
            #pragma unroll
            for (int i = 0; i < 4; i++)
                #pragma unroll
                for (int j = 0; j < 8; j++)
                    asm("fma.rn.f32x2 %0, %1, %2, %0;"
                        : "+l"(c2[i][j]) : "l"(a2[i]), "l"(b2[j]));
        }
        if (havenext) {
            #pragma unroll
            for (int q = 0; q < 4; q++) {
                At[nxt][q * 4 + 0][p0] = na[q].x; At[nxt][q * 4 + 1][p0] = na[q].y;
                At[nxt][q * 4 + 2][p0] = na[q].z; At[nxt][q * 4 + 3][p0] = na[q].w;
            }
            *(float4*)&Bs[nxt][brow][bbL] = nw;
        }
        __syncthreads();
    }

    float bv[8];
    #pragma unroll
    for (int j = 0; j < 8; j++) {
        int gn = tc * 8 + j;
        bv[j] = (bias && gn < N) ? bias[gn] : 0.f;
    }
    #pragma unroll
    for (int i = 0; i < 4; i++) {
        int gm0 = bm + tr * 8 + 2 * i;
        int gm1 = gm0 + 1;
        float lo[8], hi[8];
        #pragma unroll
        for (int j = 0; j < 8; j++) {
            float2 p = *(float2*)&c2[i][j];
            lo[j] = p.x + bv[j];
            hi[j] = p.y + bv[j];
            if (act == 1) { lo[j] = elu(lo[j]); hi[j] = elu(hi[j]); }
        }
        #pragma unroll
        for (int q = 0; q < 2; q++) {
            int gn = tc * 8 + q * 4;
            if (gn >= N) continue;
            if (gm0 < M)
                *(float4*)&C[(size_t)gm0 * ldc + gn] =
                    make_float4(lo[q * 4], lo[q * 4 + 1], lo[q * 4 + 2], lo[q * 4 + 3]);
            if (gm1 < M)
                *(float4*)&C[(size_t)gm1 * ldc + gn] =
                    make_float4(hi[q * 4], hi[q * 4 + 1], hi[q * 4 + 2], hi[q * 4 + 3]);
        }
    }
}

// per-head GEMM; azA = per-z offset applied to A (64 for head-sliced A, 0 for shared A)
__global__ void __launch_bounds__(256, 2)
sgemm256(const float* __restrict__ A, const float* __restrict__ B,
         const float* __restrict__ bias, float* __restrict__ C,
         int M, int N, int K, int lda, int ldb, int ldc, int act, int azA) {
    __shared__ __align__(16) float At[2][16][288];
    __shared__ __align__(16) float Bs[2][16][68];
    gemm_body(A + blockIdx.z * azA, B + blockIdx.z * 64,
              bias ? bias + blockIdx.z * 64 : nullptr, C + blockIdx.z * 64,
              M, N, K, lda, ldb, ldc, act, blockIdx.y * 256, At, Bs);
}

// dual GEMM: blockIdx.y < nby1 -> problem 1, else problem 2 (wave packing)
__global__ void __launch_bounds__(256, 2)
sgemm_dual(const float* __restrict__ A1, const float* __restrict__ B1,
           const float* __restrict__ b1, float* __restrict__ C1,
           int M1, int K1,
           const float* __restrict__ A2, const float* __restrict__ B2,
           const float* __restrict__ b2, float* __restrict__ C2,
           int M2, int K2, int nby1) {
    __shared__ __align__(16) float At[2][16][288];
    __shared__ __align__(16) float Bs[2][16][68];
    if ((int)blockIdx.y < nby1)
        gemm_body(A1, B1, b1, C1, M1, 64, K1, K1, 64, 64, 1, blockIdx.y * 256, At, Bs);
    else
        gemm_body(A2, B2, b2, C2, M2, 64, K2, K2, 64, 64, 1,
                  (blockIdx.y - nby1) * 256, At, Bs);
}

// ---------------- attention scalar kernels ----------------
__global__ void kvadAll5(const float* __restrict__ Wa, const float* __restrict__ asa,
                         const float* __restrict__ ada, const float* __restrict__ Wb,
                         const float* __restrict__ asb, const float* __restrict__ adb,
                         const float* __restrict__ W2, const float* __restrict__ ad2,
                         float* __restrict__ vas_a, float* __restrict__ vad_a,
                         float* __restrict__ vas_b, float* __restrict__ vad_b,
                         float* __restrict__ vad2) {
    if (blockIdx.x == 4) {
        int k = threadIdx.x;
        float s = 0.f;
        #pragma unroll
        for (int cc = 0; cc < 32; cc++) s += W2[k * 32 + cc] * ad2[cc];
        vad2[k] = s;
        return;
    }
    const float* W; const float* a; float* v;
    switch (blockIdx.x) {
        case 0: W = Wa; a = asa; v = vas_a; break;
        case 1: W = Wa; a = ada; v = vad_a; break;
        case 2: W = Wb; a = asb; v = vas_b; break;
        default: W = Wb; a = adb; v = vad_b; break;
    }
    int t = threadIdx.x;
    int h = t >> 6, k = t & 63;
    float s = 0.f;
    #pragma unroll
    for (int cc = 0; cc < 64; cc++) s += W[k * 256 + h * 64 + cc] * a[h * 64 + cc];
    v[h * 64 + k] = s;
}
__global__ void kdot2vF(const float* __restrict__ x1, const float* __restrict__ va1,
                        const float* __restrict__ vb1, float* __restrict__ oa1,
                        float* __restrict__ ob1, int n1,
                        const float* __restrict__ x2, const float* __restrict__ va2,
                        const float* __restrict__ vb2, float* __restrict__ oa2,
                        float* __restrict__ ob2, int n2) {
    int w = (blockIdx.x * blockDim.x + threadIdx.x) >> 5;
    const float* x; const float* va; const float* vb; float* oa; float* ob;
    if (w < n1) { x = x1; va = va1; vb = vb1; oa = oa1; ob = ob1; }
    else {
        w -= n1;
        if (w >= n2) return;
        x = x2; va = va2; vb = vb2; oa = oa2; ob = ob2;
    }
    int lane = threadIdx.x & 31, g = lane >> 3, r = lane & 7;
    const float* row = x + (size_t)w * 64;
    const float* v1 = va + g * 64;
    const float* v2 = vb + g * 64;
    float sa = 0.f, sb = 0.f;
    #pragma unroll
    for (int k = r; k < 64; k += 8) {
        float f = row[k];
        sa += f * v1[k];
        sb += f * v2[k];
    }
    #pragma unroll
    for (int o = 4; o; o >>= 1) {
        sa += __shfl_xor_sync(0xffffffffu, sa, o);
        sb += __shfl_xor_sync(0xffffffffu, sb, o);
    }
    if (r == 0) { oa[w * 4 + g] = sa; ob[w * 4 + g] = sb; }
}
__global__ void kals2(const float* __restrict__ hs2, const float* __restrict__ a,
                      float* __restrict__ out, int n) {
    int w = (blockIdx.x * blockDim.x + threadIdx.x) >> 5;
    if (w >= n) return;
    int lane = threadIdx.x & 31;
    float s = warp_sum(hs2[(size_t)w * 32 + lane] * a[lane]);
    if (lane == 0) out[w] = s;
}
__global__ void kald2(const float* __restrict__ t1, const float* __restrict__ v,
                      float* __restrict__ out, int n) {
    int w = (blockIdx.x * blockDim.x + threadIdx.x) >> 5;
    if (w >= n) return;
    int lane = threadIdx.x & 31;
    float s = 0.f;
    #pragma unroll
    for (int k = lane; k < 256; k += 32) s += t1[(size_t)w * 256 + k] * v[k];
    s = warp_sum(s);
    if (lane == 0) out[w] = s;
}

// ---------------- conv1 u2t: aggregate TRANSFORMED rows (1KB), fused bias+ELU ----
// t1[w, c] = elu( (1/den[h]) * sum_e exp(e_eh) * hs[src_e, c] + bias[c] ), h = c/64
__global__ void kgat_aggh(const int* __restrict__ off, const int* __restrict__ deg,
                          const int* __restrict__ csr, const float* __restrict__ hs,
                          const float* __restrict__ als, const float* __restrict__ ald,
                          const float* __restrict__ bias, float* __restrict__ out, int n) {
    int w = (blockIdx.x * blockDim.x + threadIdx.x) >> 5;
    if (w >= n) return;
    int lane = threadIdx.x & 31;
    int o = off[w], d = deg[w];
    float4 av = *(const float4*)(ald + (size_t)w * 4);
    float den0 = 0.f, den1 = 0.f, den2 = 0.f, den3 = 0.f;
    float acc[8];
    #pragma unroll
    for (int j = 0; j < 8; j++) acc[j] = 0.f;
    int i = 0;
    for (; i + 2 <= d; i += 2) {
        int s0 = csr[o + i], s1 = csr[o + i + 1];
        float4 aa = *(const float4*)(als + (size_t)s0 * 4);
        float4 ab = *(const float4*)(als + (size_t)s1 * 4);
        const float* r0 = hs + (size_t)s0 * 256;
        const float* r1 = hs + (size_t)s1 * 256;
        float f0[8], f1[8];
        #pragma unroll
        for (int j = 0; j < 8; j++) { f0[j] = r0[lane + 32 * j]; f1[j] = r1[lane + 32 * j]; }
        float ea[4], eb[4];
        ea[0] = __expf(lrelu(aa.x + av.x)); ea[1] = __expf(lrelu(aa.y + av.y));
        ea[2] = __expf(lrelu(aa.z + av.z)); ea[3] = __expf(lrelu(aa.w + av.w));
        eb[0] = __expf(lrelu(ab.x + av.x)); eb[1] = __expf(lrelu(ab.y + av.y));
        eb[2] = __expf(lrelu(ab.z + av.z)); eb[3] = __expf(lrelu(ab.w + av.w));
        den0 += ea[0] + eb[0]; den1 += ea[1] + eb[1];
        den2 += ea[2] + eb[2]; den3 += ea[3] + eb[3];
        #pragma unroll
        for (int j = 0; j < 8; j++) acc[j] += ea[j >> 1] * f0[j] + eb[j >> 1] * f1[j];
    }
    if (i < d) {
        int s0 = csr[o + i];
        float4 aa = *(const float4*)(als + (size_t)s0 * 4);
        const float* r0 = hs + (size_t)s0 * 256;
        float f0[8];
        #pragma unroll
        for (int j = 0; j < 8; j++) f0[j] = r0[lane + 32 * j];
        float ea[4];
        ea[0] = __expf(lrelu(aa.x + av.x)); ea[1] = __expf(lrelu(aa.y + av.y));
        ea[2] = __expf(lrelu(aa.z + av.z)); ea[3] = __expf(lrelu(aa.w + av.w));
        den0 += ea[0]; den1 += ea[1]; den2 += ea[2]; den3 += ea[3];
        #pragma unroll
        for (int j = 0; j < 8; j++) acc[j] += ea[j >> 1] * f0[j];
    }
    float inv[4];
    inv[0] = 1.f / (den0 + 1e-16f); inv[1] = 1.f / (den1 + 1e-16f);
    inv[2] = 1.f / (den2 + 1e-16f); inv[3] = 1.f / (den3 + 1e-16f);
    float* op = out + (size_t)w * 256;
    #pragma unroll
    for (int j = 0; j < 8; j++) {
        int c = lane + 32 * j;
        op[c] = elu(acc[j] * inv[j >> 1] + bias[c]);
    }
}

// ---------------- conv1 t2u aggregate on RAW features, 2-way unroll ----------------
__global__ void kgat_aggx(const int* __restrict__ off, const int* __restrict__ deg,
                          const int* __restrict__ csr, const float* __restrict__ x,
                          const float* __restrict__ als, const float* __restrict__ ald,
                          float* __restrict__ agg, int n) {
    int w = (blockIdx.x * blockDim.x + threadIdx.x) >> 5;
    if (w >= n) return;
    int lane = threadIdx.x & 31;
    int o = off[w], d = deg[w];
    float4 av = *(const float4*)(ald + (size_t)w * 4);
    float d0 = 0.f, d1 = 0.f, d2 = 0.f, d3 = 0.f;
    float a0l = 0.f, a0h = 0.f, a1l = 0.f, a1h = 0.f;
    float a2l = 0.f, a2h = 0.f, a3l = 0.f, a3h = 0.f;
    int i = 0;
    for (; i + 2 <= d; i += 2) {
        int s0 = csr[o + i], s1 = csr[o + i + 1];
        float4 aa = *(const float4*)(als + (size_t)s0 * 4);
        float4 ab = *(const float4*)(als + (size_t)s1 * 4);
        const float* r0 = x + (size_t)s0 * 64;
        const float* r1 = x + (size_t)s1 * 64;
        float f00 = r0[lane], f01 = r0[lane + 32];
        float f10 = r1[lane], f11 = r1[lane + 32];
        float e0a = __expf(lrelu(aa.x + av.x));
        float e1a = __expf(lrelu(aa.y + av.y));
        float e2a = __expf(lrelu(aa.z + av.z));
        float e3a = __expf(lrelu(aa.w + av.w));
        float e0b = __expf(lrelu(ab.x + av.x));
        float e1b = __expf(lrelu(ab.y + av.y));
        float e2b = __expf(lrelu(ab.z + av.z));
        float e3b = __expf(lrelu(ab.w + av.w));
        d0 += e0a + e0b; d1 += e1a + e1b; d2 += e2a + e2b; d3 += e3a + e3b;
        a0l += e0a * f00 + e0b * f10; a0h += e0a * f01 + e0b * f11;
        a1l += e1a * f00 + e1b * f10; a1h += e1a * f01 + e1b * f11;
        a2l += e2a * f00 + e2b * f10; a2h += e2a * f01 + e2b * f11;
        a3l += e3a * f00 + e3b * f10; a3h += e3a * f01 + e3b * f11;
    }
    if (i < d) {
        int s0 = csr[o + i];
        float4 aa = *(const float4*)(als + (size_t)s0 * 4);
        const float* r0 = x + (size_t)s0 * 64;
        float f00 = r0[lane], f01 = r0[lane + 32];
        float e0 = __expf(lrelu(aa.x + av.x));
        float e1 = __expf(lrelu(aa.y + av.y));
        float e2 = __expf(lrelu(aa.z + av.z));
        float e3 = __expf(lrelu(aa.w + av.w));
        d0 += e0; d1 += e1; d2 += e2; d3 += e3;
        a0l += e0 * f00; a0h += e0 * f01;
        a1l += e1 * f00; a1h += e1 * f01;
        a2l += e2 * f00; a2h += e2 * f01;
        a3l += e3 * f00; a3h += e3 * f01;
    }
    float i0 = 1.f / (d0 + 1e-16f), i1 = 1.f / (d1 + 1e-16f);
    float i2 = 1.f / (d2 + 1e-16f), i3 = 1.f / (d3 + 1e-16f);
    float* out = agg + (size_t)w * 256;
    out[lane]            = a0l * i0; out[lane + 32]       = a0h * i0;
    out[64 + lane]       = a1l * i1; out[64 + lane + 32]  = a1h * i1;
    out[128 + lane]      = a2l * i2; out[128 + lane + 32] = a2h * i2;
    out[192 + lane]      = a3l * i3; out[192 + lane + 32] = a3h * i3;
}

// ---------------- conv2 aggregate + classifier, 2-way unroll ----------------
__global__ void kgat2(const int* __restrict__ off, const int* __restrict__ deg,
                      const int* __restrict__ csr, const float* __restrict__ hs2,
                      const float* __restrict__ als2, const float* __restrict__ ald2,
                      const float* __restrict__ b2, const float* __restrict__ Wc,
                      const float* __restrict__ bc, float* __restrict__ outp, int n) {
    int w = (blockIdx.x * blockDim.x + threadIdx.x) >> 5;
    if (w >= n) return;
    int lane = threadIdx.x & 31;
    int o = off[w], d = deg[w];
    float aldv = ald2[w];
    float den = 0.f, acc = 0.f;
    int i = 0;
    for (; i + 2 <= d; i += 2) {
        int s0 = csr[o + i], s1 = csr[o + i + 1];
        float al0 = als2[s0], al1 = als2[s1];
        float h0 = hs2[(size_t)s0 * 32 + lane], h1 = hs2[(size_t)s1 * 32 + lane];
        float e0 = __expf(lrelu(al0 + aldv));
        float e1 = __expf(lrelu(al1 + aldv));
        den += e0 + e1;
        acc += e0 * h0 + e1 * h1;
    }
    if (i < d) {
        int s0 = csr[o + i];
        float e0 = __expf(lrelu(als2[s0] + aldv));
        den += e0;
        acc += e0 * hs2[(size_t)s0 * 32 + lane];
    }
    float t = elu(acc / (den + 1e-16f) + b2[lane]);
    float p = warp_sum(t * Wc[lane]);
    if (lane == 0) outp[w] = p + bc[0];
}

// ---------------- launch ----------------
extern "C" void kernel_launch(void* const* d_in, const int* in_sizes, int n_in,
                              void* d_out, int out_size) {
    const float* x_tx   = (const float*)d_in[0];
    const float* x_us   = (const float*)d_in[1];
    const int*   ei_u2t = (const int*)d_in[2];
    const int*   ei_t2u = (const int*)d_in[3];
    const float* Wp_tx  = (const float*)d_in[4];
    const float* bp_tx  = (const float*)d_in[5];
    const float* Wp_us  = (const float*)d_in[6];
    const float* bp_us  = (const float*)d_in[7];
    const float* W1_u2t = (const float*)d_in[8];
    const float* as1_u2t= (const float*)d_in[9];
    const float* ad1_u2t= (const float*)d_in[10];
    const float* b1_u2t = (const float*)d_in[11];
    const float* W2_u2t = (const float*)d_in[12];
    const float* as2_u2t= (const float*)d_in[13];
    const float* ad2_u2t= (const float*)d_in[14];
    const float* b2_u2t = (const float*)d_in[15];
    const float* W1_t2u = (const float*)d_in[16];
    const float* as1_t2u= (const float*)d_in[17];
    const float* ad1_t2u= (const float*)d_in[18];
    const float* b1_t2u = (const float*)d_in[19];
    const float* Wc     = (const float*)d_in[24];
    const float* bc     = (const float*)d_in[25];
    const int E = in_sizes[2] / 2;

    float *p_h_tx, *p_h_us, *p_hs_u2t, *p_agg_u, *p_t1, *p_u1, *p_hs2;
    float *p_als_u2t, *p_ald_u2t, *p_als_t2u, *p_ald_t2u, *p_als2, *p_ald2;
    float *p_vas_u2t, *p_vad_u2t, *p_vas_t2u, *p_vad_t2u, *p_vad2;
    int *p_deg_t, *p_off_t, *p_cnt_t, *p_deg_u, *p_off_u, *p_cnt_u;
    int *p_csr_t, *p_csr_u, *p_sums_t, *p_sums_u;
    cudaGetSymbolAddress((void**)&p_h_tx, g_h_tx);
    cudaGetSymbolAddress((void**)&p_h_us, g_h_us);
    cudaGetSymbolAddress((void**)&p_hs_u2t, g_hs_u2t);
    cudaGetSymbolAddress((void**)&p_agg_u, g_agg_u);
    cudaGetSymbolAddress((void**)&p_t1, g_t1);
    cudaGetSymbolAddress((void**)&p_u1, g_u1);
    cudaGetSymbolAddress((void**)&p_hs2, g_hs2);
    cudaGetSymbolAddress((void**)&p_als_u2t, g_als_u2t);
    cudaGetSymbolAddress((void**)&p_ald_u2t, g_ald_u2t);
    cudaGetSymbolAddress((void**)&p_als_t2u, g_als_t2u);
    cudaGetSymbolAddress((void**)&p_ald_t2u, g_ald_t2u);
    cudaGetSymbolAddress((void**)&p_als2, g_als2);
    cudaGetSymbolAddress((void**)&p_ald2, g_ald2);
    cudaGetSymbolAddress((void**)&p_vas_u2t, g_vas_u2t);
    cudaGetSymbolAddress((void**)&p_vad_u2t, g_vad_u2t);
    cudaGetSymbolAddress((void**)&p_vas_t2u, g_vas_t2u);
    cudaGetSymbolAddress((void**)&p_vad_t2u, g_vad_t2u);
    cudaGetSymbolAddress((void**)&p_vad2, g_vad2);
    cudaGetSymbolAddress((void**)&p_deg_t, g_deg_t);
    cudaGetSymbolAddress((void**)&p_off_t, g_off_t);
    cudaGetSymbolAddress((void**)&p_cnt_t, g_cnt_t);
    cudaGetSymbolAddress((void**)&p_deg_u, g_deg_u);
    cudaGetSymbolAddress((void**)&p_off_u, g_off_u);
    cudaGetSymbolAddress((void**)&p_cnt_u, g_cnt_u);
    cudaGetSymbolAddress((void**)&p_csr_t, g_csr_t);
    cudaGetSymbolAddress((void**)&p_csr_u, g_csr_u);
    cudaGetSymbolAddress((void**)&p_sums_t, g_sums_t);
    cudaGetSymbolAddress((void**)&p_sums_u, g_sums_u);

    // lazy host-handle init (host objects only; first call is the non-captured
    // correctness run, so creation never happens inside graph capture)
    static cudaStream_t s2 = nullptr;
    static cudaEvent_t ev0 = nullptr, evP = nullptr, evCSR = nullptr, evT = nullptr;
    if (s2 == nullptr) {
        cudaStreamCreateWithFlags(&s2, cudaStreamNonBlocking);
        cudaEventCreateWithFlags(&ev0, cudaEventDisableTiming);
        cudaEventCreateWithFlags(&evP, cudaEventDisableTiming);
        cudaEventCreateWithFlags(&evCSR, cudaEventDisableTiming);
        cudaEventCreateWithFlags(&evT, cudaEventDisableTiming);
    }

    const int nbt = (NTX + 1023) / 1024, nbu = (NUS + 1023) / 1024;
    const int nby_t = (NTX + 255) / 256, nby_u = (NUS + 255) / 256;

    // fork
    cudaEventRecord(ev0, 0);
    cudaStreamWaitEvent(s2, ev0, 0);

    // ---- NULL stream: CSR chain start ---- (launches 1-3)
    kzero<<<(NTX + 255) / 256, 256>>>(p_deg_t, NTX, p_cnt_t, NTX, p_deg_u, NUS, p_cnt_u, NUS);
    khist2<<<(2 * E + 255) / 256, 256>>>(ei_u2t, ei_t2u, p_deg_t, p_deg_u, E);
    kscan1m<<<nbt + nbu, 1024>>>(p_deg_t, p_off_t, p_sums_t, NTX,
                                 p_deg_u, p_off_u, p_sums_u, NUS, nbt);
    // ---- s2 head: fused projections (launch 4 = profiled) -> hs_u2t -> scalars ----
    sgemm_dual<<<dim3(1, nby_t + nby_u, 1), 256, 0, s2>>>(
        x_tx, Wp_tx, bp_tx, p_h_tx, NTX, 128,
        x_us, Wp_us, bp_us, p_h_us, NUS, 64, nby_t);
    // hs_u2t = h_us @ W1_u2t (transform-first; per-head z, shared A)
    sgemm256<<<dim3(1, nby_u, 4), 256, 0, s2>>>(p_h_us, W1_u2t, nullptr, p_hs_u2t,
                                                NUS, 64, 64, 64, 256, 256, 0, 0);
    kvadAll5<<<5, 256, 0, s2>>>(W1_u2t, as1_u2t, ad1_u2t, W1_t2u, as1_t2u, ad1_t2u,
                                W2_u2t, ad2_u2t,
                                p_vas_u2t, p_vad_u2t, p_vas_t2u, p_vad_t2u, p_vad2);
    kdot2vF<<<(NTX + NUS + 7) / 8, 256, 0, s2>>>(
        p_h_tx, p_vad_u2t, p_vas_t2u, p_ald_u2t, p_als_t2u, NTX,
        p_h_us, p_vas_u2t, p_vad_t2u, p_als_u2t, p_ald_t2u, NUS);
    cudaEventRecord(evP, s2);

    // ---- NULL stream: finish CSR ----
    kscan2m<<<2, 1024>>>(p_sums_t, nbt, p_sums_u, nbu);
    kscan3m<<<nbt + nbu, 1024>>>(p_off_t, p_sums_t, NTX, p_off_u, p_sums_u, NUS, nbt);
    kscatter2<<<(2 * E + 255) / 256, 256>>>(ei_u2t, ei_t2u, p_off_t, p_cnt_t, p_csr_t,
                                            p_off_u, p_cnt_u, p_csr_u, E);
    cudaEventRecord(evCSR, 0);

    // ---- branch T (s2): aggregate transformed rows -> t1 (fused bias+ELU) -> kald2 ----
    cudaStreamWaitEvent(s2, evCSR, 0);
    kgat_aggh<<<(NTX + 7) / 8, 256, 0, s2>>>(p_off_t, p_deg_t, p_csr_t, p_hs_u2t,
                                             p_als_u2t, p_ald_u2t, b1_u2t, p_t1, NTX);
    kald2<<<(NTX + 7) / 8, 256, 0, s2>>>(p_t1, p_vad2, p_ald2, NTX);
    cudaEventRecord(evT, s2);

    // ---- branch U (NULL): aggx_u -> tfm_u -> hs2 -> kals2 ----
    cudaStreamWaitEvent(0, evP, 0);
    kgat_aggx<<<(NUS + 7) / 8, 256>>>(p_off_u, p_deg_u, p_csr_u, p_h_tx,
                                      p_als_t2u, p_ald_t2u, p_agg_u, NUS);
    sgemm256<<<dim3(1, nby_u, 4), 256>>>(p_agg_u, W1_t2u, b1_t2u, p_u1,
                                         NUS, 64, 64, 256, 256, 256, 1, 64);
    sgemm256<<<dim3(1, nby_u, 1), 256>>>(p_u1, W2_u2t, nullptr, p_hs2,
                                         NUS, 32, 256, 256, 32, 32, 0, 0);
    kals2<<<(NUS + 7) / 8, 256>>>(p_hs2, as2_u2t, p_als2, NUS);

    // ---- join + final (NULL) ----
    cudaStreamWaitEvent(0, evT, 0);
    kgat2<<<(NTX + 7) / 8, 256>>>(p_off_t, p_deg_t, p_csr_t, p_hs2, p_als2, p_ald2,
                                  b2_u2t, Wc, bc, (float*)d_out, NTX);
}

// round 14
// speedup vs baseline: 1.0301x; 1.0301x over previous
#include <cuda_runtime.h>

#define NTX 100000
#define NUS 50000
#define NEG 500000

typedef unsigned long long u64t;

// ---------------- scratch (static device globals; no allocation) ----------------
__device__ float g_h_tx[NTX * 64];
__device__ float g_h_us[NUS * 64];
__device__ float g_hs_u2t[NUS * 256];  // transform-first source features (u2t)
__device__ float g_agg_u[NUS * 256];
__device__ float g_t1[NTX * 256];
__device__ float g_u1[NUS * 256];
__device__ float g_hs2[NUS * 32];
__device__ float g_als_u2t[NUS * 4];
__device__ float g_ald_u2t[NTX * 4];
__device__ float g_als_t2u[NTX * 4];
__device__ float g_ald_t2u[NUS * 4];
__device__ float g_als2[NUS];
__device__ float g_ald2[NTX];
__device__ float g_vas_u2t[256];
__device__ float g_vad_u2t[256];
__device__ float g_vas_t2u[256];
__device__ float g_vad_t2u[256];
__device__ float g_vad2[256];
__device__ int g_deg_t[NTX], g_off_t[NTX], g_cnt_t[NTX];
__device__ int g_deg_u[NUS], g_off_u[NUS], g_cnt_u[NUS];
__device__ int g_csr_t[NEG], g_csr_u[NEG];
__device__ int g_sums_t[1024], g_sums_u[1024];

// ---------------- helpers ----------------
__device__ __forceinline__ float warp_sum(float v) {
    #pragma unroll
    for (int o = 16; o; o >>= 1) v += __shfl_xor_sync(0xffffffffu, v, o);
    return v;
}
__device__ __forceinline__ float lrelu(float x) { return x > 0.f ? x : 0.2f * x; }
__device__ __forceinline__ float elu(float x)   { return x > 0.f ? x : expm1f(x); }
__device__ __forceinline__ u64t pack2(float x) {
    u64t r;
    unsigned u = __float_as_uint(x);
    asm("mov.b64 %0, {%1, %1};" : "=l"(r) : "r"(u));
    return r;
}

// ---------------- CSR build (merged both directions) ----------------
__global__ void kzero(int* __restrict__ a, int na, int* __restrict__ b, int nb,
                      int* __restrict__ c, int nc, int* __restrict__ d, int nd) {
    int i = blockIdx.x * blockDim.x + threadIdx.x;
    if (i < na) a[i] = 0;
    if (i < nb) b[i] = 0;
    if (i < nc) c[i] = 0;
    if (i < nd) d[i] = 0;
}
__global__ void khist2(const int* __restrict__ ei_u2t, const int* __restrict__ ei_t2u,
                       int* __restrict__ deg_t, int* __restrict__ deg_u, int E) {
    int i = blockIdx.x * blockDim.x + threadIdx.x;
    if (i < E)               atomicAdd(&deg_t[ei_u2t[E + i]], 1);
    else if (i < 2 * E)      atomicAdd(&deg_u[ei_t2u[E + (i - E)]], 1);
}
__global__ void kscan1m(const int* __restrict__ in_t, int* __restrict__ out_t,
                        int* __restrict__ sums_t, int nt,
                        const int* __restrict__ in_u, int* __restrict__ out_u,
                        int* __restrict__ sums_u, int nu, int nbt) {
    __shared__ int sh[1024];
    const int* in; int* out; int* sums; int n; int b;
    if (blockIdx.x < nbt) { in = in_t; out = out_t; sums = sums_t; n = nt; b = blockIdx.x; }
    else                  { in = in_u; out = out_u; sums = sums_u; n = nu; b = blockIdx.x - nbt; }
    int i = b * 1024 + threadIdx.x;
    int v = (i < n) ? in[i] : 0;
    sh[threadIdx.x] = v;
    __syncthreads();
    for (int s = 1; s < 1024; s <<= 1) {
        int t = (threadIdx.x >= s) ? sh[threadIdx.x - s] : 0;
        __syncthreads();
        sh[threadIdx.x] += t;
        __syncthreads();
    }
    if (i < n) out[i] = sh[threadIdx.x] - v;
    if (threadIdx.x == 1023) sums[b] = sh[1023];
}
__global__ void kscan2m(int* __restrict__ sums_t, int nbt,
                        int* __restrict__ sums_u, int nbu) {
    __shared__ int sh[1024];
    int* sums = (blockIdx.x == 0) ? sums_t : sums_u;
    int nb = (blockIdx.x == 0) ? nbt : nbu;
    int v = (threadIdx.x < nb) ? sums[threadIdx.x] : 0;
    sh[threadIdx.x] = v;
    __syncthreads();
    for (int s = 1; s < 1024; s <<= 1) {
        int t = (threadIdx.x >= s) ? sh[threadIdx.x - s] : 0;
        __syncthreads();
        sh[threadIdx.x] += t;
        __syncthreads();
    }
    if (threadIdx.x < nb) sums[threadIdx.x] = sh[threadIdx.x] - v;
}
__global__ void kscan3m(int* __restrict__ out_t, const int* __restrict__ sums_t, int nt,
                        int* __restrict__ out_u, const int* __restrict__ sums_u, int nu,
                        int nbt) {
    int* out; const int* sums; int n; int b;
    if (blockIdx.x < nbt) { out = out_t; sums = sums_t; n = nt; b = blockIdx.x; }
    else                  { out = out_u; sums = sums_u; n = nu; b = blockIdx.x - nbt; }
    int i = b * 1024 + threadIdx.x;
    if (i < n) out[i] += sums[b];
}
__global__ void kscatter2(const int* __restrict__ ei_u2t, const int* __restrict__ ei_t2u,
                          const int* __restrict__ off_t, int* __restrict__ cnt_t,
                          int* __restrict__ csr_t,
                          const int* __restrict__ off_u, int* __restrict__ cnt_u,
                          int* __restrict__ csr_u, int E) {
    int i = blockIdx.x * blockDim.x + threadIdx.x;
    if (i < E) {
        int d = ei_u2t[E + i];
        int p = atomicAdd(&cnt_t[d], 1);
        csr_t[off_t[d] + p] = ei_u2t[i];
    } else if (i < 2 * E) {
        int j = i - E;
        int d = ei_t2u[E + j];
        int p = atomicAdd(&cnt_u[d], 1);
        csr_u[off_u[d] + p] = ei_t2u[j];
    }
}

// ---------------- FFMA2 SGEMM core ----------------
#define APHYS(m) ((m) + (((m) >> 4) << 1))
#define BPHYS(c) ((c) + ((((c) >> 5) & 1) << 2))

__device__ __forceinline__ void gemm_body(
    const float* __restrict__ A, const float* __restrict__ B,
    const float* __restrict__ bias, float* __restrict__ C,
    int M, int N, int K, int lda, int ldb, int ldc, int act, int bm,
    float (&At)[2][16][288], float (&Bs)[2][16][68]) {
    const int tid = threadIdx.x;
    const int tr = tid >> 3;
    const int tc = tid & 7;
    const int brow = tid >> 4;
    const int bcolL = (tid & 15) * 4;
    const int bcol = tc * 8;
    const int abase2 = tr * 4 + (tr >> 1);
    const int bbL = BPHYS(bcolL);
    const int bb = BPHYS(bcol);

    u64t c2[4][8];
    #pragma unroll
    for (int i = 0; i < 4; i++)
        #pragma unroll
        for (int j = 0; j < 8; j++) c2[i][j] = 0ull;

    const int r0 = bm + tid;
    const bool v0ok = r0 < M;
    const float* A0 = v0ok ? (A + (size_t)r0 * lda) : A;
    const int p0 = APHYS(tid);
    const int NK = K >> 4;

    {
        #pragma unroll
        for (int q = 0; q < 4; q++) {
            float4 a0 = v0ok ? *(const float4*)(A0 + q * 4) : make_float4(0.f, 0.f, 0.f, 0.f);
            At[0][q * 4 + 0][p0] = a0.x; At[0][q * 4 + 1][p0] = a0.y;
            At[0][q * 4 + 2][p0] = a0.z; At[0][q * 4 + 3][p0] = a0.w;
        }
        float4 w = (bcolL < N) ? *(const float4*)(B + (size_t)brow * ldb + bcolL)
                               : make_float4(0.f, 0.f, 0.f, 0.f);
        *(float4*)&Bs[0][brow][bbL] = w;
    }
    __syncthreads();

    for (int t = 0; t < NK; t++) {
        const int cur = t & 1, nxt = cur ^ 1;
        float4 na[4], nw;
        bool havenext = (t + 1 < NK);
        if (havenext) {
            const int k0 = (t + 1) << 4;
            #pragma unroll
            for (int q = 0; q < 4; q++)
                na[q] = v0ok ? *(const float4*)(A0 + k0 + q * 4) : make_float4(0.f, 0.f, 0.f, 0.f);
            nw = (bcolL < N) ? *(const float4*)(B + (size_t)(k0 + brow) * ldb + bcolL)
                             : make_float4(0.f, 0.f, 0.f, 0.f);
        }
        #pragma unroll
        for (int k = 0; k < 16; k++) {
            u64t a2[4];
            const u64t* Ap = (const u64t*)&At[cur][k][0];
            #pragma unroll
            for (int i = 0; i < 4; i++) a2[i] = Ap[abase2 + i];
            float4 w0 = *(const float4*)&Bs[cur][k][bb];
            float4 w1 = *(const float4*)&Bs[cur][k][bb + 4];
            u64t b2[8];
            b2[0] = pack2(w0.x); b2[1] = pack2(w0.y); b2[2] = pack2(w0.z); b2[3] = pack2(w0.w);
            b2[4] = pack2(w1.x); b2[5] = pack2(w1.y); b2[6] = pack2(w1.z); b2[7] = pack2(w1.w);
            #pragma unroll
            for (int i = 0; i < 4; i++)
                #pragma unroll
                for (int j = 0; j < 8; j++)
                    asm("fma.rn.f32x2 %0, %1, %2, %0;"
                        : "+l"(c2[i][j]) : "l"(a2[i]), "l"(b2[j]));
        }
        if (havenext) {
            #pragma unroll
            for (int q = 0; q < 4; q++) {
                At[nxt][q * 4 + 0][p0] = na[q].x; At[nxt][q * 4 + 1][p0] = na[q].y;
                At[nxt][q * 4 + 2][p0] = na[q].z; At[nxt][q * 4 + 3][p0] = na[q].w;
            }
            *(float4*)&Bs[nxt][brow][bbL] = nw;
        }
        __syncthreads();
    }

    float bv[8];
    #pragma unroll
    for (int j = 0; j < 8; j++) {
        int gn = tc * 8 + j;
        bv[j] = (bias && gn < N) ? bias[gn] : 0.f;
    }
    #pragma unroll
    for (int i = 0; i < 4; i++) {
        int gm0 = bm + tr * 8 + 2 * i;
        int gm1 = gm0 + 1;
        float lo[8], hi[8];
        #pragma unroll
        for (int j = 0; j < 8; j++) {
            float2 p = *(float2*)&c2[i][j];
            lo[j] = p.x + bv[j];
            hi[j] = p.y + bv[j];
            if (act == 1) { lo[j] = elu(lo[j]); hi[j] = elu(hi[j]); }
        }
        #pragma unroll
        for (int q = 0; q < 2; q++) {
            int gn = tc * 8 + q * 4;
            if (gn >= N) continue;
            if (gm0 < M)
                *(float4*)&C[(size_t)gm0 * ldc + gn] =
                    make_float4(lo[q * 4], lo[q * 4 + 1], lo[q * 4 + 2], lo[q * 4 + 3]);
            if (gm1 < M)
                *(float4*)&C[(size_t)gm1 * ldc + gn] =
                    make_float4(hi[q * 4], hi[q * 4 + 1], hi[q * 4 + 2], hi[q * 4 + 3]);
        }
    }
}

// per-head GEMM; azA = per-z offset applied to A (64 for head-sliced A, 0 for shared A)
__global__ void __launch_bounds__(256, 2)
sgemm256(const float* __restrict__ A, const float* __restrict__ B,
         const float* __restrict__ bias, float* __restrict__ C,
         int M, int N, int K, int lda, int ldb, int ldc, int act, int azA) {
    __shared__ __align__(16) float At[2][16][288];
    __shared__ __align__(16) float Bs[2][16][68];
    gemm_body(A + blockIdx.z * azA, B + blockIdx.z * 64,
              bias ? bias + blockIdx.z * 64 : nullptr, C + blockIdx.z * 64,
              M, N, K, lda, ldb, ldc, act, blockIdx.y * 256, At, Bs);
}

// dual GEMM: blockIdx.y < nby1 -> problem 1, else problem 2 (wave packing)
__global__ void __launch_bounds__(256, 2)
sgemm_dual(const float* __restrict__ A1, const float* __restrict__ B1,
           const float* __restrict__ b1, float* __restrict__ C1,
           int M1, int K1,
           const float* __restrict__ A2, const float* __restrict__ B2,
           const float* __restrict__ b2, float* __restrict__ C2,
           int M2, int K2, int nby1) {
    __shared__ __align__(16) float At[2][16][288];
    __shared__ __align__(16) float Bs[2][16][68];
    if ((int)blockIdx.y < nby1)
        gemm_body(A1, B1, b1, C1, M1, 64, K1, K1, 64, 64, 1, blockIdx.y * 256, At, Bs);
    else
        gemm_body(A2, B2, b2, C2, M2, 64, K2, K2, 64, 64, 1,
                  (blockIdx.y - nby1) * 256, At, Bs);
}

// ---------------- attention scalar kernels ----------------
__global__ void kvadAll5(const float* __restrict__ Wa, const float* __restrict__ asa,
                         const float* __restrict__ ada, const float* __restrict__ Wb,
                         const float* __restrict__ asb, const float* __restrict__ adb,
                         const float* __restrict__ W2, const float* __restrict__ ad2,
                         float* __restrict__ vas_a, float* __restrict__ vad_a,
                         float* __restrict__ vas_b, float* __restrict__ vad_b,
                         float* __restrict__ vad2) {
    if (blockIdx.x == 4) {
        int k = threadIdx.x;
        float s = 0.f;
        #pragma unroll
        for (int cc = 0; cc < 32; cc++) s += W2[k * 32 + cc] * ad2[cc];
        vad2[k] = s;
        return;
    }
    const float* W; const float* a; float* v;
    switch (blockIdx.x) {
        case 0: W = Wa; a = asa; v = vas_a; break;
        case 1: W = Wa; a = ada; v = vad_a; break;
        case 2: W = Wb; a = asb; v = vas_b; break;
        default: W = Wb; a = adb; v = vad_b; break;
    }
    int t = threadIdx.x;
    int h = t >> 6, k = t & 63;
    float s = 0.f;
    #pragma unroll
    for (int cc = 0; cc < 64; cc++) s += W[k * 256 + h * 64 + cc] * a[h * 64 + cc];
    v[h * 64 + k] = s;
}
__global__ void kdot2vF(const float* __restrict__ x1, const float* __restrict__ va1,
                        const float* __restrict__ vb1, float* __restrict__ oa1,
                        float* __restrict__ ob1, int n1,
                        const float* __restrict__ x2, const float* __restrict__ va2,
                        const float* __restrict__ vb2, float* __restrict__ oa2,
                        float* __restrict__ ob2, int n2) {
    int w = (blockIdx.x * blockDim.x + threadIdx.x) >> 5;
    const float* x; const float* va; const float* vb; float* oa; float* ob;
    if (w < n1) { x = x1; va = va1; vb = vb1; oa = oa1; ob = ob1; }
    else {
        w -= n1;
        if (w >= n2) return;
        x = x2; va = va2; vb = vb2; oa = oa2; ob = ob2;
    }
    int lane = threadIdx.x & 31, g = lane >> 3, r = lane & 7;
    const float* row = x + (size_t)w * 64;
    const float* v1 = va + g * 64;
    const float* v2 = vb + g * 64;
    float sa = 0.f, sb = 0.f;
    #pragma unroll
    for (int k = r; k < 64; k += 8) {
        float f = row[k];
        sa += f * v1[k];
        sb += f * v2[k];
    }
    #pragma unroll
    for (int o = 4; o; o >>= 1) {
        sa += __shfl_xor_sync(0xffffffffu, sa, o);
        sb += __shfl_xor_sync(0xffffffffu, sb, o);
    }
    if (r == 0) { oa[w * 4 + g] = sa; ob[w * 4 + g] = sb; }
}
__global__ void kals2(const float* __restrict__ hs2, const float* __restrict__ a,
                      float* __restrict__ out, int n) {
    int w = (blockIdx.x * blockDim.x + threadIdx.x) >> 5;
    if (w >= n) return;
    int lane = threadIdx.x & 31;
    float s = warp_sum(hs2[(size_t)w * 32 + lane] * a[lane]);
    if (lane == 0) out[w] = s;
}

// ---------------- conv1 u2t: aggregate TRANSFORMED rows, fused bias+ELU,
// AND fused conv2 ald2 dot (ald2[w] = dot(t1[w,:], vad2)) ----------------
__global__ void kgat_aggh(const int* __restrict__ off, const int* __restrict__ deg,
                          const int* __restrict__ csr, const float* __restrict__ hs,
                          const float* __restrict__ als, const float* __restrict__ ald,
                          const float* __restrict__ bias, const float* __restrict__ vad2,
                          float* __restrict__ out, float* __restrict__ ald2, int n) {
    int w = (blockIdx.x * blockDim.x + threadIdx.x) >> 5;
    if (w >= n) return;
    int lane = threadIdx.x & 31;
    int o = off[w], d = deg[w];
    float4 av = *(const float4*)(ald + (size_t)w * 4);
    float den0 = 0.f, den1 = 0.f, den2 = 0.f, den3 = 0.f;
    float acc[8];
    #pragma unroll
    for (int j = 0; j < 8; j++) acc[j] = 0.f;
    int i = 0;
    for (; i + 2 <= d; i += 2) {
        int s0 = csr[o + i], s1 = csr[o + i + 1];
        float4 aa = *(const float4*)(als + (size_t)s0 * 4);
        float4 ab = *(const float4*)(als + (size_t)s1 * 4);
        const float* r0 = hs + (size_t)s0 * 256;
        const float* r1 = hs + (size_t)s1 * 256;
        float f0[8], f1[8];
        #pragma unroll
        for (int j = 0; j < 8; j++) { f0[j] = r0[lane + 32 * j]; f1[j] = r1[lane + 32 * j]; }
        float ea[4], eb[4];
        ea[0] = __expf(lrelu(aa.x + av.x)); ea[1] = __expf(lrelu(aa.y + av.y));
        ea[2] = __expf(lrelu(aa.z + av.z)); ea[3] = __expf(lrelu(aa.w + av.w));
        eb[0] = __expf(lrelu(ab.x + av.x)); eb[1] = __expf(lrelu(ab.y + av.y));
        eb[2] = __expf(lrelu(ab.z + av.z)); eb[3] = __expf(lrelu(ab.w + av.w));
        den0 += ea[0] + eb[0]; den1 += ea[1] + eb[1];
        den2 += ea[2] + eb[2]; den3 += ea[3] + eb[3];
        #pragma unroll
        for (int j = 0; j < 8; j++) acc[j] += ea[j >> 1] * f0[j] + eb[j >> 1] * f1[j];
    }
    if (i < d) {
        int s0 = csr[o + i];
        float4 aa = *(const float4*)(als + (size_t)s0 * 4);
        const float* r0 = hs + (size_t)s0 * 256;
        float f0[8];
        #pragma unroll
        for (int j = 0; j < 8; j++) f0[j] = r0[lane + 32 * j];
        float ea[4];
        ea[0] = __expf(lrelu(aa.x + av.x)); ea[1] = __expf(lrelu(aa.y + av.y));
        ea[2] = __expf(lrelu(aa.z + av.z)); ea[3] = __expf(lrelu(aa.w + av.w));
        den0 += ea[0]; den1 += ea[1]; den2 += ea[2]; den3 += ea[3];
        #pragma unroll
        for (int j = 0; j < 8; j++) acc[j] += ea[j >> 1] * f0[j];
    }
    float inv[4];
    inv[0] = 1.f / (den0 + 1e-16f); inv[1] = 1.f / (den1 + 1e-16f);
    inv[2] = 1.f / (den2 + 1e-16f); inv[3] = 1.f / (den3 + 1e-16f);
    float* op = out + (size_t)w * 256;
    float dotv = 0.f;
    #pragma unroll
    for (int j = 0; j < 8; j++) {
        int c = lane + 32 * j;
        float val = elu(acc[j] * inv[j >> 1] + bias[c]);
        op[c] = val;
        dotv += val * vad2[c];
    }
    dotv = warp_sum(dotv);
    if (lane == 0) ald2[w] = dotv;
}

// ---------------- conv1 t2u aggregate on RAW features, 2-way unroll ----------------
__global__ void kgat_aggx(const int* __restrict__ off, const int* __restrict__ deg,
                          const int* __restrict__ csr, const float* __restrict__ x,
                          const float* __restrict__ als, const float* __restrict__ ald,
                          float* __restrict__ agg, int n) {
    int w = (blockIdx.x * blockDim.x + threadIdx.x) >> 5;
    if (w >= n) return;
    int lane = threadIdx.x & 31;
    int o = off[w], d = deg[w];
    float4 av = *(const float4*)(ald + (size_t)w * 4);
    float d0 = 0.f, d1 = 0.f, d2 = 0.f, d3 = 0.f;
    float a0l = 0.f, a0h = 0.f, a1l = 0.f, a1h = 0.f;
    float a2l = 0.f, a2h = 0.f, a3l = 0.f, a3h = 0.f;
    int i = 0;
    for (; i + 2 <= d; i += 2) {
        int s0 = csr[o + i], s1 = csr[o + i + 1];
        float4 aa = *(const float4*)(als + (size_t)s0 * 4);
        float4 ab = *(const float4*)(als + (size_t)s1 * 4);
        const float* r0 = x + (size_t)s0 * 64;
        const float* r1 = x + (size_t)s1 * 64;
        float f00 = r0[lane], f01 = r0[lane + 32];
        float f10 = r1[lane], f11 = r1[lane + 32];
        float e0a = __expf(lrelu(aa.x + av.x));
        float e1a = __expf(lrelu(aa.y + av.y));
        float e2a = __expf(lrelu(aa.z + av.z));
        float e3a = __expf(lrelu(aa.w + av.w));
        float e0b = __expf(lrelu(ab.x + av.x));
        float e1b = __expf(lrelu(ab.y + av.y));
        float e2b = __expf(lrelu(ab.z + av.z));
        float e3b = __expf(lrelu(ab.w + av.w));
        d0 += e0a + e0b; d1 += e1a + e1b; d2 += e2a + e2b; d3 += e3a + e3b;
        a0l += e0a * f00 + e0b * f10; a0h += e0a * f01 + e0b * f11;
        a1l += e1a * f00 + e1b * f10; a1h += e1a * f01 + e1b * f11;
        a2l += e2a * f00 + e2b * f10; a2h += e2a * f01 + e2b * f11;
        a3l += e3a * f00 + e3b * f10; a3h += e3a * f01 + e3b * f11;
    }
    if (i < d) {
        int s0 = csr[o + i];
        float4 aa = *(const float4*)(als + (size_t)s0 * 4);
        const float* r0 = x + (size_t)s0 * 64;
        float f00 = r0[lane], f01 = r0[lane + 32];
        float e0 = __expf(lrelu(aa.x + av.x));
        float e1 = __expf(lrelu(aa.y + av.y));
        float e2 = __expf(lrelu(aa.z + av.z));
        float e3 = __expf(lrelu(aa.w + av.w));
        d0 += e0; d1 += e1; d2 += e2; d3 += e3;
        a0l += e0 * f00; a0h += e0 * f01;
        a1l += e1 * f00; a1h += e1 * f01;
        a2l += e2 * f00; a2h += e2 * f01;
        a3l += e3 * f00; a3h += e3 * f01;
    }
    float i0 = 1.f / (d0 + 1e-16f), i1 = 1.f / (d1 + 1e-16f);
    float i2 = 1.f / (d2 + 1e-16f), i3 = 1.f / (d3 + 1e-16f);
    float* out = agg + (size_t)w * 256;
    out[lane]            = a0l * i0; out[lane + 32]       = a0h * i0;
    out[64 + lane]       = a1l * i1; out[64 + lane + 32]  = a1h * i1;
    out[128 + lane]      = a2l * i2; out[128 + lane + 32] = a2h * i2;
    out[192 + lane]      = a3l * i3; out[192 + lane + 32] = a3h * i3;
}

// ---------------- conv2 aggregate + classifier, 2-way unroll ----------------
__global__ void kgat2(const int* __restrict__ off, const int* __restrict__ deg,
                      const int* __restrict__ csr, const float* __restrict__ hs2,
                      const float* __restrict__ als2, const float* __restrict__ ald2,
                      const float* __restrict__ b2, const float* __restrict__ Wc,
                      const float* __restrict__ bc, float* __restrict__ outp, int n) {
    int w = (blockIdx.x * blockDim.x + threadIdx.x) >> 5;
    if (w >= n) return;
    int lane = threadIdx.x & 31;
    int o = off[w], d = deg[w];
    float aldv = ald2[w];
    float den = 0.f, acc = 0.f;
    int i = 0;
    for (; i + 2 <= d; i += 2) {
        int s0 = csr[o + i], s1 = csr[o + i + 1];
        float al0 = als2[s0], al1 = als2[s1];
        float h0 = hs2[(size_t)s0 * 32 + lane], h1 = hs2[(size_t)s1 * 32 + lane];
        float e0 = __expf(lrelu(al0 + aldv));
        float e1 = __expf(lrelu(al1 + aldv));
        den += e0 + e1;
        acc += e0 * h0 + e1 * h1;
    }
    if (i < d) {
        int s0 = csr[o + i];
        float e0 = __expf(lrelu(als2[s0] + aldv));
        den += e0;
        acc += e0 * hs2[(size_t)s0 * 32 + lane];
    }
    float t = elu(acc / (den + 1e-16f) + b2[lane]);
    float p = warp_sum(t * Wc[lane]);
    if (lane == 0) outp[w] = p + bc[0];
}

// ---------------- launch ----------------
extern "C" void kernel_launch(void* const* d_in, const int* in_sizes, int n_in,
                              void* d_out, int out_size) {
    const float* x_tx   = (const float*)d_in[0];
    const float* x_us   = (const float*)d_in[1];
    const int*   ei_u2t = (const int*)d_in[2];
    const int*   ei_t2u = (const int*)d_in[3];
    const float* Wp_tx  = (const float*)d_in[4];
    const float* bp_tx  = (const float*)d_in[5];
    const float* Wp_us  = (const float*)d_in[6];
    const float* bp_us  = (const float*)d_in[7];
    const float* W1_u2t = (const float*)d_in[8];
    const float* as1_u2t= (const float*)d_in[9];
    const float* ad1_u2t= (const float*)d_in[10];
    const float* b1_u2t = (const float*)d_in[11];
    const float* W2_u2t = (const float*)d_in[12];
    const float* as2_u2t= (const float*)d_in[13];
    const float* ad2_u2t= (const float*)d_in[14];
    const float* b2_u2t = (const float*)d_in[15];
    const float* W1_t2u = (const float*)d_in[16];
    const float* as1_t2u= (const float*)d_in[17];
    const float* ad1_t2u= (const float*)d_in[18];
    const float* b1_t2u = (const float*)d_in[19];
    const float* Wc     = (const float*)d_in[24];
    const float* bc     = (const float*)d_in[25];
    const int E = in_sizes[2] / 2;

    float *p_h_tx, *p_h_us, *p_hs_u2t, *p_agg_u, *p_t1, *p_u1, *p_hs2;
    float *p_als_u2t, *p_ald_u2t, *p_als_t2u, *p_ald_t2u, *p_als2, *p_ald2;
    float *p_vas_u2t, *p_vad_u2t, *p_vas_t2u, *p_vad_t2u, *p_vad2;
    int *p_deg_t, *p_off_t, *p_cnt_t, *p_deg_u, *p_off_u, *p_cnt_u;
    int *p_csr_t, *p_csr_u, *p_sums_t, *p_sums_u;
    cudaGetSymbolAddress((void**)&p_h_tx, g_h_tx);
    cudaGetSymbolAddress((void**)&p_h_us, g_h_us);
    cudaGetSymbolAddress((void**)&p_hs_u2t, g_hs_u2t);
    cudaGetSymbolAddress((void**)&p_agg_u, g_agg_u);
    cudaGetSymbolAddress((void**)&p_t1, g_t1);
    cudaGetSymbolAddress((void**)&p_u1, g_u1);
    cudaGetSymbolAddress((void**)&p_hs2, g_hs2);
    cudaGetSymbolAddress((void**)&p_als_u2t, g_als_u2t);
    cudaGetSymbolAddress((void**)&p_ald_u2t, g_ald_u2t);
    cudaGetSymbolAddress((void**)&p_als_t2u, g_als_t2u);
    cudaGetSymbolAddress((void**)&p_ald_t2u, g_ald_t2u);
    cudaGetSymbolAddress((void**)&p_als2, g_als2);
    cudaGetSymbolAddress((void**)&p_ald2, g_ald2);
    cudaGetSymbolAddress((void**)&p_vas_u2t, g_vas_u2t);
    cudaGetSymbolAddress((void**)&p_vad_u2t, g_vad_u2t);
    cudaGetSymbolAddress((void**)&p_vas_t2u, g_vas_t2u);
    cudaGetSymbolAddress((void**)&p_vad_t2u, g_vad_t2u);
    cudaGetSymbolAddress((void**)&p_vad2, g_vad2);
    cudaGetSymbolAddress((void**)&p_deg_t, g_deg_t);
    cudaGetSymbolAddress((void**)&p_off_t, g_off_t);
    cudaGetSymbolAddress((void**)&p_cnt_t, g_cnt_t);
    cudaGetSymbolAddress((void**)&p_deg_u, g_deg_u);
    cudaGetSymbolAddress((void**)&p_off_u, g_off_u);
    cudaGetSymbolAddress((void**)&p_cnt_u, g_cnt_u);
    cudaGetSymbolAddress((void**)&p_csr_t, g_csr_t);
    cudaGetSymbolAddress((void**)&p_csr_u, g_csr_u);
    cudaGetSymbolAddress((void**)&p_sums_t, g_sums_t);
    cudaGetSymbolAddress((void**)&p_sums_u, g_sums_u);

    // lazy host-handle init (host objects only; first call is the non-captured
    // correctness run, so creation never happens inside graph capture)
    static cudaStream_t s2 = nullptr;
    static cudaEvent_t ev0 = nullptr, evH = nullptr, evP = nullptr,
                       evHS = nullptr, evT = nullptr;
    if (s2 == nullptr) {
        cudaStreamCreateWithFlags(&s2, cudaStreamNonBlocking);
        cudaEventCreateWithFlags(&ev0, cudaEventDisableTiming);
        cudaEventCreateWithFlags(&evH, cudaEventDisableTiming);
        cudaEventCreateWithFlags(&evP, cudaEventDisableTiming);
        cudaEventCreateWithFlags(&evHS, cudaEventDisableTiming);
        cudaEventCreateWithFlags(&evT, cudaEventDisableTiming);
    }

    const int nbt = (NTX + 1023) / 1024, nbu = (NUS + 1023) / 1024;
    const int nby_t = (NTX + 255) / 256, nby_u = (NUS + 255) / 256;

    // fork
    cudaEventRecord(ev0, 0);
    cudaStreamWaitEvent(s2, ev0, 0);

    // ---- NULL stream: CSR chain start ---- (launches 1-3)
    kzero<<<(NTX + 255) / 256, 256>>>(p_deg_t, NTX, p_cnt_t, NTX, p_deg_u, NUS, p_cnt_u, NUS);
    khist2<<<(2 * E + 255) / 256, 256>>>(ei_u2t, ei_t2u, p_deg_t, p_deg_u, E);
    kscan1m<<<nbt + nbu, 1024>>>(p_deg_t, p_off_t, p_sums_t, NTX,
                                 p_deg_u, p_off_u, p_sums_u, NUS, nbt);
    // ---- s2 head: fused projections (launch 4 = profiled) ----
    sgemm_dual<<<dim3(1, nby_t + nby_u, 1), 256, 0, s2>>>(
        x_tx, Wp_tx, bp_tx, p_h_tx, NTX, 128,
        x_us, Wp_us, bp_us, p_h_us, NUS, 64, nby_t);
    cudaEventRecord(evH, s2);
    // ---- NULL stream: finish CSR ----
    kscan2m<<<2, 1024>>>(p_sums_t, nbt, p_sums_u, nbu);
    kscan3m<<<nbt + nbu, 1024>>>(p_off_t, p_sums_t, NTX, p_off_u, p_sums_u, NUS, nbt);
    kscatter2<<<(2 * E + 255) / 256, 256>>>(ei_u2t, ei_t2u, p_off_t, p_cnt_t, p_csr_t,
                                            p_off_u, p_cnt_u, p_csr_u, E);
    // ---- s2: attention scalars (concurrent with NULL's hs GEMM) ----
    kvadAll5<<<5, 256, 0, s2>>>(W1_u2t, as1_u2t, ad1_u2t, W1_t2u, as1_t2u, ad1_t2u,
                                W2_u2t, ad2_u2t,
                                p_vas_u2t, p_vad_u2t, p_vas_t2u, p_vad_t2u, p_vad2);
    kdot2vF<<<(NTX + NUS + 7) / 8, 256, 0, s2>>>(
        p_h_tx, p_vad_u2t, p_vas_t2u, p_ald_u2t, p_als_t2u, NTX,
        p_h_us, p_vas_u2t, p_vad_t2u, p_als_u2t, p_ald_t2u, NUS);
    cudaEventRecord(evP, s2);
    // ---- NULL: hs_u2t = h_us @ W1_u2t (overlaps s2's kvad/kdot) ----
    cudaStreamWaitEvent(0, evH, 0);
    sgemm256<<<dim3(1, nby_u, 4), 256>>>(p_h_us, W1_u2t, nullptr, p_hs_u2t,
                                         NUS, 64, 64, 64, 256, 256, 0, 0);
    cudaEventRecord(evHS, 0);

    // ---- branch T (s2): aggh (fused bias+ELU+ald2 dot) ----
    cudaStreamWaitEvent(s2, evHS, 0);
    kgat_aggh<<<(NTX + 7) / 8, 256, 0, s2>>>(p_off_t, p_deg_t, p_csr_t, p_hs_u2t,
                                             p_als_u2t, p_ald_u2t, b1_u2t, p_vad2,
                                             p_t1, p_ald2, NTX);
    cudaEventRecord(evT, s2);

    // ---- branch U (NULL): aggx_u -> tfm_u -> hs2 -> kals2 ----
    cudaStreamWaitEvent(0, evP, 0);
    kgat_aggx<<<(NUS + 7) / 8, 256>>>(p_off_u, p_deg_u, p_csr_u, p_h_tx,
                                      p_als_t2u, p_ald_t2u, p_agg_u, NUS);
    sgemm256<<<dim3(1, nby_u, 4), 256>>>(p_agg_u, W1_t2u, b1_t2u, p_u1,
                                         NUS, 64, 64, 256, 256, 256, 1, 64);
    sgemm256<<<dim3(1, nby_u, 1), 256>>>(p_u1, W2_u2t, nullptr, p_hs2,
                                         NUS, 32, 256, 256, 32, 32, 0, 0);
    kals2<<<(NUS + 7) / 8, 256>>>(p_hs2, as2_u2t, p_als2, NUS);

    // ---- join + final (NULL) ----
    cudaStreamWaitEvent(0, evT, 0);
    kgat2<<<(NTX + 7) / 8, 256>>>(p_off_t, p_deg_t, p_csr_t, p_hs2, p_als2, p_ald2,
                                  b2_u2t, Wc, bc, (float*)d_out, NTX);
}

// round 15
// speedup vs baseline: 1.0392x; 1.0088x over previous
#include <cuda_runtime.h>

#define NTX 100000
#define NUS 50000
#define NEG 500000

typedef unsigned long long u64t;

// ---------------- scratch (static device globals; no allocation) ----------------
__device__ float g_h_tx[NTX * 64];
__device__ float g_h_us[NUS * 64];
__device__ float g_hs_u2t[NUS * 256];  // transform-first source features (u2t)
__device__ float g_agg_u[NUS * 256];
__device__ float g_u1[NUS * 256];
__device__ float g_hs2[NUS * 32];
__device__ float g_als_u2t[NUS * 4];
__device__ float g_ald_u2t[NTX * 4];
__device__ float g_als_t2u[NTX * 4];
__device__ float g_ald_t2u[NUS * 4];
__device__ float g_ald2[NTX];
__device__ float g_vas_u2t[256];
__device__ float g_vad_u2t[256];
__device__ float g_vas_t2u[256];
__device__ float g_vad_t2u[256];
__device__ float g_vad2[256];
__device__ int g_deg_t[NTX], g_off_t[NTX], g_cnt_t[NTX];
__device__ int g_deg_u[NUS], g_off_u[NUS], g_cnt_u[NUS];
__device__ int g_csr_t[NEG], g_csr_u[NEG];
__device__ int g_sums_t[1024], g_sums_u[1024];

// ---------------- helpers ----------------
__device__ __forceinline__ float warp_sum(float v) {
    #pragma unroll
    for (int o = 16; o; o >>= 1) v += __shfl_xor_sync(0xffffffffu, v, o);
    return v;
}
__device__ __forceinline__ float lrelu(float x) { return x > 0.f ? x : 0.2f * x; }
__device__ __forceinline__ float elu(float x)   { return x > 0.f ? x : expm1f(x); }
__device__ __forceinline__ u64t pack2(float x) {
    u64t r;
    unsigned u = __float_as_uint(x);
    asm("mov.b64 %0, {%1, %1};" : "=l"(r) : "r"(u));
    return r;
}

// ---------------- CSR build (merged both directions) ----------------
__global__ void kzero(int* __restrict__ a, int na, int* __restrict__ b, int nb,
                      int* __restrict__ c, int nc, int* __restrict__ d, int nd) {
    int i = blockIdx.x * blockDim.x + threadIdx.x;
    if (i < na) a[i] = 0;
    if (i < nb) b[i] = 0;
    if (i < nc) c[i] = 0;
    if (i < nd) d[i] = 0;
}
__global__ void khist2(const int* __restrict__ ei_u2t, const int* __restrict__ ei_t2u,
                       int* __restrict__ deg_t, int* __restrict__ deg_u, int E) {
    int i = blockIdx.x * blockDim.x + threadIdx.x;
    if (i < E)               atomicAdd(&deg_t[ei_u2t[E + i]], 1);
    else if (i < 2 * E)      atomicAdd(&deg_u[ei_t2u[E + (i - E)]], 1);
}
__global__ void kscan1m(const int* __restrict__ in_t, int* __restrict__ out_t,
                        int* __restrict__ sums_t, int nt,
                        const int* __restrict__ in_u, int* __restrict__ out_u,
                        int* __restrict__ sums_u, int nu, int nbt) {
    __shared__ int sh[1024];
    const int* in; int* out; int* sums; int n; int b;
    if (blockIdx.x < nbt) { in = in_t; out = out_t; sums = sums_t; n = nt; b = blockIdx.x; }
    else                  { in = in_u; out = out_u; sums = sums_u; n = nu; b = blockIdx.x - nbt; }
    int i = b * 1024 + threadIdx.x;
    int v = (i < n) ? in[i] : 0;
    sh[threadIdx.x] = v;
    __syncthreads();
    for (int s = 1; s < 1024; s <<= 1) {
        int t = (threadIdx.x >= s) ? sh[threadIdx.x - s] : 0;
        __syncthreads();
        sh[threadIdx.x] += t;
        __syncthreads();
    }
    if (i < n) out[i] = sh[threadIdx.x] - v;
    if (threadIdx.x == 1023) sums[b] = sh[1023];
}
__global__ void kscan2m(int* __restrict__ sums_t, int nbt,
                        int* __restrict__ sums_u, int nbu) {
    __shared__ int sh[1024];
    int* sums = (blockIdx.x == 0) ? sums_t : sums_u;
    int nb = (blockIdx.x == 0) ? nbt : nbu;
    int v = (threadIdx.x < nb) ? sums[threadIdx.x] : 0;
    sh[threadIdx.x] = v;
    __syncthreads();
    for (int s = 1; s < 1024; s <<= 1) {
        int t = (threadIdx.x >= s) ? sh[threadIdx.x - s] : 0;
        __syncthreads();
        sh[threadIdx.x] += t;
        __syncthreads();
    }
    if (threadIdx.x < nb) sums[threadIdx.x] = sh[threadIdx.x] - v;
}
__global__ void kscan3m(int* __restrict__ out_t, const int* __restrict__ sums_t, int nt,
                        int* __restrict__ out_u, const int* __restrict__ sums_u, int nu,
                        int nbt) {
    int* out; const int* sums; int n; int b;
    if (blockIdx.x < nbt) { out = out_t; sums = sums_t; n = nt; b = blockIdx.x; }
    else                  { out = out_u; sums = sums_u; n = nu; b = blockIdx.x - nbt; }
    int i = b * 1024 + threadIdx.x;
    if (i < n) out[i] += sums[b];
}
__global__ void kscatter2(const int* __restrict__ ei_u2t, const int* __restrict__ ei_t2u,
                          const int* __restrict__ off_t, int* __restrict__ cnt_t,
                          int* __restrict__ csr_t,
                          const int* __restrict__ off_u, int* __restrict__ cnt_u,
                          int* __restrict__ csr_u, int E) {
    int i = blockIdx.x * blockDim.x + threadIdx.x;
    if (i < E) {
        int d = ei_u2t[E + i];
        int p = atomicAdd(&cnt_t[d], 1);
        csr_t[off_t[d] + p] = ei_u2t[i];
    } else if (i < 2 * E) {
        int j = i - E;
        int d = ei_t2u[E + j];
        int p = atomicAdd(&cnt_u[d], 1);
        csr_u[off_u[d] + p] = ei_t2u[j];
    }
}

// ---------------- FFMA2 SGEMM core ----------------
#define APHYS(m) ((m) + (((m) >> 4) << 1))
#define BPHYS(c) ((c) + ((((c) >> 5) & 1) << 2))

__device__ __forceinline__ void gemm_body(
    const float* __restrict__ A, const float* __restrict__ B,
    const float* __restrict__ bias, float* __restrict__ C,
    int M, int N, int K, int lda, int ldb, int ldc, int act, int bm,
    float (&At)[2][16][288], float (&Bs)[2][16][68]) {
    const int tid = threadIdx.x;
    const int tr = tid >> 3;
    const int tc = tid & 7;
    const int brow = tid >> 4;
    const int bcolL = (tid & 15) * 4;
    const int bcol = tc * 8;
    const int abase2 = tr * 4 + (tr >> 1);
    const int bbL = BPHYS(bcolL);
    const int bb = BPHYS(bcol);

    u64t c2[4][8];
    #pragma unroll
    for (int i = 0; i < 4; i++)
        #pragma unroll
        for (int j = 0; j < 8; j++) c2[i][j] = 0ull;

    const int r0 = bm + tid;
    const bool v0ok = r0 < M;
    const float* A0 = v0ok ? (A + (size_t)r0 * lda) : A;
    const int p0 = APHYS(tid);
    const int NK = K >> 4;

    {
        #pragma unroll
        for (int q = 0; q < 4; q++) {
            float4 a0 = v0ok ? *(const float4*)(A0 + q * 4) : make_float4(0.f, 0.f, 0.f, 0.f);
            At[0][q * 4 + 0][p0] = a0.x; At[0][q * 4 + 1][p0] = a0.y;
            At[0][q * 4 + 2][p0] = a0.z; At[0][q * 4 + 3][p0] = a0.w;
        }
        float4 w = (bcolL < N) ? *(const float4*)(B + (size_t)brow * ldb + bcolL)
                               : make_float4(0.f, 0.f, 0.f, 0.f);
        *(float4*)&Bs[0][brow][bbL] = w;
    }
    __syncthreads();

    for (int t = 0; t < NK; t++) {
        const int cur = t & 1, nxt = cur ^ 1;
        float4 na[4], nw;
        bool havenext = (t + 1 < NK);
        if (havenext) {
            const int k0 = (t + 1) << 4;
            #pragma unroll
            for (int q = 0; q < 4; q++)
                na[q] = v0ok ? *(const float4*)(A0 + k0 + q * 4) : make_float4(0.f, 0.f, 0.f, 0.f);
            nw = (bcolL < N) ? *(const float4*)(B + (size_t)(k0 + brow) * ldb + bcolL)
                             : make_float4(0.f, 0.f, 0.f, 0.f);
        }
        #pragma unroll
        for (int k = 0; k < 16; k++) {
            u64t a2[4];
            const u64t* Ap = (const u64t*)&At[cur][k][0];
            #pragma unroll
            for (int i = 0; i < 4; i++) a2[i] = Ap[abase2 + i];
            float4 w0 = *(const float4*)&Bs[cur][k][bb];
            float4 w1 = *(const float4*)&Bs[cur][k][bb + 4];
            u64t b2[8];
            b2[0] = pack2(w0.x); b2[1] = pack2(w0.y); b2[2] = pack2(w0.z); b2[3] = pack2(w0.w);
            b2[4] = pack2(w1.x); b2[5] = pack2(w1.y); b2[6] = pack2(w1.z); b2[7] = pack2(w1.w);
            #pragma unroll
            for (int i = 0; i < 4; i++)
                #pragma unroll
                for (int j = 0; j < 8; j++)
                    asm("fma.rn.f32x2 %0, %1, %2, %0;"
                        : "+l"(c2[i][j]) : "l"(a2[i]), "l"(b2[j]));
        }
        if (havenext) {
            #pragma unroll
            for (int q = 0; q < 4; q++) {
                At[nxt][q * 4 + 0][p0] = na[q].x; At[nxt][q * 4 + 1][p0] = na[q].y;
                At[nxt][q * 4 + 2][p0] = na[q].z; At[nxt][q * 4 + 3][p0] = na[q].w;
            }
            *(float4*)&Bs[nxt][brow][bbL] = nw;
        }
        __syncthreads();
    }

    float bv[8];
    #pragma unroll
    for (int j = 0; j < 8; j++) {
        int gn = tc * 8 + j;
        bv[j] = (bias && gn < N) ? bias[gn] : 0.f;
    }
    #pragma unroll
    for (int i = 0; i < 4; i++) {
        int gm0 = bm + tr * 8 + 2 * i;
        int gm1 = gm0 + 1;
        float lo[8], hi[8];
        #pragma unroll
        for (int j = 0; j < 8; j++) {
            float2 p = *(float2*)&c2[i][j];
            lo[j] = p.x + bv[j];
            hi[j] = p.y + bv[j];
            if (act == 1) { lo[j] = elu(lo[j]); hi[j] = elu(hi[j]); }
        }
        #pragma unroll
        for (int q = 0; q < 2; q++) {
            int gn = tc * 8 + q * 4;
            if (gn >= N) continue;
            if (gm0 < M)
                *(float4*)&C[(size_t)gm0 * ldc + gn] =
                    make_float4(lo[q * 4], lo[q * 4 + 1], lo[q * 4 + 2], lo[q * 4 + 3]);
            if (gm1 < M)
                *(float4*)&C[(size_t)gm1 * ldc + gn] =
                    make_float4(hi[q * 4], hi[q * 4 + 1], hi[q * 4 + 2], hi[q * 4 + 3]);
        }
    }
}

// per-head GEMM; azA = per-z offset applied to A (64 for head-sliced A, 0 for shared A)
__global__ void __launch_bounds__(256, 2)
sgemm256(const float* __restrict__ A, const float* __restrict__ B,
         const float* __restrict__ bias, float* __restrict__ C,
         int M, int N, int K, int lda, int ldb, int ldc, int act, int azA) {
    __shared__ __align__(16) float At[2][16][288];
    __shared__ __align__(16) float Bs[2][16][68];
    gemm_body(A + blockIdx.z * azA, B + blockIdx.z * 64,
              bias ? bias + blockIdx.z * 64 : nullptr, C + blockIdx.z * 64,
              M, N, K, lda, ldb, ldc, act, blockIdx.y * 256, At, Bs);
}

// dual GEMM: blockIdx.y < nby1 -> problem 1, else problem 2 (wave packing)
__global__ void __launch_bounds__(256, 2)
sgemm_dual(const float* __restrict__ A1, const float* __restrict__ B1,
           const float* __restrict__ b1, float* __restrict__ C1,
           int M1, int K1,
           const float* __restrict__ A2, const float* __restrict__ B2,
           const float* __restrict__ b2, float* __restrict__ C2,
           int M2, int K2, int nby1) {
    __shared__ __align__(16) float At[2][16][288];
    __shared__ __align__(16) float Bs[2][16][68];
    if ((int)blockIdx.y < nby1)
        gemm_body(A1, B1, b1, C1, M1, 64, K1, K1, 64, 64, 1, blockIdx.y * 256, At, Bs);
    else
        gemm_body(A2, B2, b2, C2, M2, 64, K2, K2, 64, 64, 1,
                  (blockIdx.y - nby1) * 256, At, Bs);
}

// ---------------- attention scalar kernels ----------------
__global__ void kvadAll5(const float* __restrict__ Wa, const float* __restrict__ asa,
                         const float* __restrict__ ada, const float* __restrict__ Wb,
                         const float* __restrict__ asb, const float* __restrict__ adb,
                         const float* __restrict__ W2, const float* __restrict__ ad2,
                         float* __restrict__ vas_a, float* __restrict__ vad_a,
                         float* __restrict__ vas_b, float* __restrict__ vad_b,
                         float* __restrict__ vad2) {
    if (blockIdx.x == 4) {
        int k = threadIdx.x;
        float s = 0.f;
        #pragma unroll
        for (int cc = 0; cc < 32; cc++) s += W2[k * 32 + cc] * ad2[cc];
        vad2[k] = s;
        return;
    }
    const float* W; const float* a; float* v;
    switch (blockIdx.x) {
        case 0: W = Wa; a = asa; v = vas_a; break;
        case 1: W = Wa; a = ada; v = vad_a; break;
        case 2: W = Wb; a = asb; v = vas_b; break;
        default: W = Wb; a = adb; v = vad_b; break;
    }
    int t = threadIdx.x;
    int h = t >> 6, k = t & 63;
    float s = 0.f;
    #pragma unroll
    for (int cc = 0; cc < 64; cc++) s += W[k * 256 + h * 64 + cc] * a[h * 64 + cc];
    v[h * 64 + k] = s;
}
__global__ void kdot2vF(const float* __restrict__ x1, const float* __restrict__ va1,
                        const float* __restrict__ vb1, float* __restrict__ oa1,
                        float* __restrict__ ob1, int n1,
                        const float* __restrict__ x2, const float* __restrict__ va2,
                        const float* __restrict__ vb2, float* __restrict__ oa2,
                        float* __restrict__ ob2, int n2) {
    int w = (blockIdx.x * blockDim.x + threadIdx.x) >> 5;
    const float* x; const float* va; const float* vb; float* oa; float* ob;
    if (w < n1) { x = x1; va = va1; vb = vb1; oa = oa1; ob = ob1; }
    else {
        w -= n1;
        if (w >= n2) return;
        x = x2; va = va2; vb = vb2; oa = oa2; ob = ob2;
    }
    int lane = threadIdx.x & 31, g = lane >> 3, r = lane & 7;
    const float* row = x + (size_t)w * 64;
    const float* v1 = va + g * 64;
    const float* v2 = vb + g * 64;
    float sa = 0.f, sb = 0.f;
    #pragma unroll
    for (int k = r; k < 64; k += 8) {
        float f = row[k];
        sa += f * v1[k];
        sb += f * v2[k];
    }
    #pragma unroll
    for (int o = 4; o; o >>= 1) {
        sa += __shfl_xor_sync(0xffffffffu, sa, o);
        sb += __shfl_xor_sync(0xffffffffu, sb, o);
    }
    if (r == 0) { oa[w * 4 + g] = sa; ob[w * 4 + g] = sb; }
}

// ---------------- conv1 u2t: aggregate TRANSFORMED rows; t1 NEVER materialized.
// Produces ONLY ald2[w] = dot(elu(agg*inv + bias), vad2). ----------------
__global__ void kgat_aggh(const int* __restrict__ off, const int* __restrict__ deg,
                          const int* __restrict__ csr, const float* __restrict__ hs,
                          const float* __restrict__ als, const float* __restrict__ ald,
                          const float* __restrict__ bias, const float* __restrict__ vad2,
                          float* __restrict__ ald2, int n) {
    int w = (blockIdx.x * blockDim.x + threadIdx.x) >> 5;
    if (w >= n) return;
    int lane = threadIdx.x & 31;
    int o = off[w], d = deg[w];
    float4 av = *(const float4*)(ald + (size_t)w * 4);
    float den0 = 0.f, den1 = 0.f, den2 = 0.f, den3 = 0.f;
    float acc[8];
    #pragma unroll
    for (int j = 0; j < 8; j++) acc[j] = 0.f;
    int i = 0;
    for (; i + 2 <= d; i += 2) {
        int s0 = csr[o + i], s1 = csr[o + i + 1];
        float4 aa = *(const float4*)(als + (size_t)s0 * 4);
        float4 ab = *(const float4*)(als + (size_t)s1 * 4);
        const float* r0 = hs + (size_t)s0 * 256;
        const float* r1 = hs + (size_t)s1 * 256;
        float f0[8], f1[8];
        #pragma unroll
        for (int j = 0; j < 8; j++) { f0[j] = r0[lane + 32 * j]; f1[j] = r1[lane + 32 * j]; }
        float ea[4], eb[4];
        ea[0] = __expf(lrelu(aa.x + av.x)); ea[1] = __expf(lrelu(aa.y + av.y));
        ea[2] = __expf(lrelu(aa.z + av.z)); ea[3] = __expf(lrelu(aa.w + av.w));
        eb[0] = __expf(lrelu(ab.x + av.x)); eb[1] = __expf(lrelu(ab.y + av.y));
        eb[2] = __expf(lrelu(ab.z + av.z)); eb[3] = __expf(lrelu(ab.w + av.w));
        den0 += ea[0] + eb[0]; den1 += ea[1] + eb[1];
        den2 += ea[2] + eb[2]; den3 += ea[3] + eb[3];
        #pragma unroll
        for (int j = 0; j < 8; j++) acc[j] += ea[j >> 1] * f0[j] + eb[j >> 1] * f1[j];
    }
    if (i < d) {
        int s0 = csr[o + i];
        float4 aa = *(const float4*)(als + (size_t)s0 * 4);
        const float* r0 = hs + (size_t)s0 * 256;
        float f0[8];
        #pragma unroll
        for (int j = 0; j < 8; j++) f0[j] = r0[lane + 32 * j];
        float ea[4];
        ea[0] = __expf(lrelu(aa.x + av.x)); ea[1] = __expf(lrelu(aa.y + av.y));
        ea[2] = __expf(lrelu(aa.z + av.z)); ea[3] = __expf(lrelu(aa.w + av.w));
        den0 += ea[0]; den1 += ea[1]; den2 += ea[2]; den3 += ea[3];
        #pragma unroll
        for (int j = 0; j < 8; j++) acc[j] += ea[j >> 1] * f0[j];
    }
    float inv[4];
    inv[0] = 1.f / (den0 + 1e-16f); inv[1] = 1.f / (den1 + 1e-16f);
    inv[2] = 1.f / (den2 + 1e-16f); inv[3] = 1.f / (den3 + 1e-16f);
    float dotv = 0.f;
    #pragma unroll
    for (int j = 0; j < 8; j++) {
        int c = lane + 32 * j;
        float val = elu(acc[j] * inv[j >> 1] + bias[c]);
        dotv += val * vad2[c];
    }
    dotv = warp_sum(dotv);
    if (lane == 0) ald2[w] = dotv;
}

// ---------------- conv1 t2u aggregate on RAW features, 2-way unroll ----------------
__global__ void kgat_aggx(const int* __restrict__ off, const int* __restrict__ deg,
                          const int* __restrict__ csr, const float* __restrict__ x,
                          const float* __restrict__ als, const float* __restrict__ ald,
                          float* __restrict__ agg, int n) {
    int w = (blockIdx.x * blockDim.x + threadIdx.x) >> 5;
    if (w >= n) return;
    int lane = threadIdx.x & 31;
    int o = off[w], d = deg[w];
    float4 av = *(const float4*)(ald + (size_t)w * 4);
    float d0 = 0.f, d1 = 0.f, d2 = 0.f, d3 = 0.f;
    float a0l = 0.f, a0h = 0.f, a1l = 0.f, a1h = 0.f;
    float a2l = 0.f, a2h = 0.f, a3l = 0.f, a3h = 0.f;
    int i = 0;
    for (; i + 2 <= d; i += 2) {
        int s0 = csr[o + i], s1 = csr[o + i + 1];
        float4 aa = *(const float4*)(als + (size_t)s0 * 4);
        float4 ab = *(const float4*)(als + (size_t)s1 * 4);
        const float* r0 = x + (size_t)s0 * 64;
        const float* r1 = x + (size_t)s1 * 64;
        float f00 = r0[lane], f01 = r0[lane + 32];
        float f10 = r1[lane], f11 = r1[lane + 32];
        float e0a = __expf(lrelu(aa.x + av.x));
        float e1a = __expf(lrelu(aa.y + av.y));
        float e2a = __expf(lrelu(aa.z + av.z));
        float e3a = __expf(lrelu(aa.w + av.w));
        float e0b = __expf(lrelu(ab.x + av.x));
        float e1b = __expf(lrelu(ab.y + av.y));
        float e2b = __expf(lrelu(ab.z + av.z));
        float e3b = __expf(lrelu(ab.w + av.w));
        d0 += e0a + e0b; d1 += e1a + e1b; d2 += e2a + e2b; d3 += e3a + e3b;
        a0l += e0a * f00 + e0b * f10; a0h += e0a * f01 + e0b * f11;
        a1l += e1a * f00 + e1b * f10; a1h += e1a * f01 + e1b * f11;
        a2l += e2a * f00 + e2b * f10; a2h += e2a * f01 + e2b * f11;
        a3l += e3a * f00 + e3b * f10; a3h += e3a * f01 + e3b * f11;
    }
    if (i < d) {
        int s0 = csr[o + i];
        float4 aa = *(const float4*)(als + (size_t)s0 * 4);
        const float* r0 = x + (size_t)s0 * 64;
        float f00 = r0[lane], f01 = r0[lane + 32];
        float e0 = __expf(lrelu(aa.x + av.x));
        float e1 = __expf(lrelu(aa.y + av.y));
        float e2 = __expf(lrelu(aa.z + av.z));
        float e3 = __expf(lrelu(aa.w + av.w));
        d0 += e0; d1 += e1; d2 += e2; d3 += e3;
        a0l += e0 * f00; a0h += e0 * f01;
        a1l += e1 * f00; a1h += e1 * f01;
        a2l += e2 * f00; a2h += e2 * f01;
        a3l += e3 * f00; a3h += e3 * f01;
    }
    float i0 = 1.f / (d0 + 1e-16f), i1 = 1.f / (d1 + 1e-16f);
    float i2 = 1.f / (d2 + 1e-16f), i3 = 1.f / (d3 + 1e-16f);
    float* out = agg + (size_t)w * 256;
    out[lane]            = a0l * i0; out[lane + 32]       = a0h * i0;
    out[64 + lane]       = a1l * i1; out[64 + lane + 32]  = a1h * i1;
    out[128 + lane]      = a2l * i2; out[128 + lane + 32] = a2h * i2;
    out[192 + lane]      = a3l * i3; out[192 + lane + 32] = a3h * i3;
}

// ---------------- conv2 aggregate + classifier, fused inline als2 ----------------
// als2[s] = warp_sum(hs2[s,:] * as2) computed per edge from the already-loaded row.
__global__ void kgat2(const int* __restrict__ off, const int* __restrict__ deg,
                      const int* __restrict__ csr, const float* __restrict__ hs2,
                      const float* __restrict__ as2, const float* __restrict__ ald2,
                      const float* __restrict__ b2, const float* __restrict__ Wc,
                      const float* __restrict__ bc, float* __restrict__ outp, int n) {
    int w = (blockIdx.x * blockDim.x + threadIdx.x) >> 5;
    if (w >= n) return;
    int lane = threadIdx.x & 31;
    int o = off[w], d = deg[w];
    float aldv = ald2[w];
    float a2v = as2[lane];
    float den = 0.f, acc = 0.f;
    int i = 0;
    for (; i + 2 <= d; i += 2) {
        int s0 = csr[o + i], s1 = csr[o + i + 1];
        float h0 = hs2[(size_t)s0 * 32 + lane], h1 = hs2[(size_t)s1 * 32 + lane];
        float al0 = warp_sum(h0 * a2v);
        float al1 = warp_sum(h1 * a2v);
        float e0 = __expf(lrelu(al0 + aldv));
        float e1 = __expf(lrelu(al1 + aldv));
        den += e0 + e1;
        acc += e0 * h0 + e1 * h1;
    }
    if (i < d) {
        int s0 = csr[o + i];
        float h0 = hs2[(size_t)s0 * 32 + lane];
        float al0 = warp_sum(h0 * a2v);
        float e0 = __expf(lrelu(al0 + aldv));
        den += e0;
        acc += e0 * h0;
    }
    float t = elu(acc / (den + 1e-16f) + b2[lane]);
    float p = warp_sum(t * Wc[lane]);
    if (lane == 0) outp[w] = p + bc[0];
}

// ---------------- launch ----------------
extern "C" void kernel_launch(void* const* d_in, const int* in_sizes, int n_in,
                              void* d_out, int out_size) {
    const float* x_tx   = (const float*)d_in[0];
    const float* x_us   = (const float*)d_in[1];
    const int*   ei_u2t = (const int*)d_in[2];
    const int*   ei_t2u = (const int*)d_in[3];
    const float* Wp_tx  = (const float*)d_in[4];
    const float* bp_tx  = (const float*)d_in[5];
    const float* Wp_us  = (const float*)d_in[6];
    const float* bp_us  = (const float*)d_in[7];
    const float* W1_u2t = (const float*)d_in[8];
    const float* as1_u2t= (const float*)d_in[9];
    const float* ad1_u2t= (const float*)d_in[10];
    const float* b1_u2t = (const float*)d_in[11];
    const float* W2_u2t = (const float*)d_in[12];
    const float* as2_u2t= (const float*)d_in[13];
    const float* ad2_u2t= (const float*)d_in[14];
    const float* b2_u2t = (const float*)d_in[15];
    const float* W1_t2u = (const float*)d_in[16];
    const float* as1_t2u= (const float*)d_in[17];
    const float* ad1_t2u= (const float*)d_in[18];
    const float* b1_t2u = (const float*)d_in[19];
    const float* Wc     = (const float*)d_in[24];
    const float* bc     = (const float*)d_in[25];
    const int E = in_sizes[2] / 2;

    float *p_h_tx, *p_h_us, *p_hs_u2t, *p_agg_u, *p_u1, *p_hs2;
    float *p_als_u2t, *p_ald_u2t, *p_als_t2u, *p_ald_t2u, *p_ald2;
    float *p_vas_u2t, *p_vad_u2t, *p_vas_t2u, *p_vad_t2u, *p_vad2;
    int *p_deg_t, *p_off_t, *p_cnt_t, *p_deg_u, *p_off_u, *p_cnt_u;
    int *p_csr_t, *p_csr_u, *p_sums_t, *p_sums_u;
    cudaGetSymbolAddress((void**)&p_h_tx, g_h_tx);
    cudaGetSymbolAddress((void**)&p_h_us, g_h_us);
    cudaGetSymbolAddress((void**)&p_hs_u2t, g_hs_u2t);
    cudaGetSymbolAddress((void**)&p_agg_u, g_agg_u);
    cudaGetSymbolAddress((void**)&p_u1, g_u1);
    cudaGetSymbolAddress((void**)&p_hs2, g_hs2);
    cudaGetSymbolAddress((void**)&p_als_u2t, g_als_u2t);
    cudaGetSymbolAddress((void**)&p_ald_u2t, g_ald_u2t);
    cudaGetSymbolAddress((void**)&p_als_t2u, g_als_t2u);
    cudaGetSymbolAddress((void**)&p_ald_t2u, g_ald_t2u);
    cudaGetSymbolAddress((void**)&p_ald2, g_ald2);
    cudaGetSymbolAddress((void**)&p_vas_u2t, g_vas_u2t);
    cudaGetSymbolAddress((void**)&p_vad_u2t, g_vad_u2t);
    cudaGetSymbolAddress((void**)&p_vas_t2u, g_vas_t2u);
    cudaGetSymbolAddress((void**)&p_vad_t2u, g_vad_t2u);
    cudaGetSymbolAddress((void**)&p_vad2, g_vad2);
    cudaGetSymbolAddress((void**)&p_deg_t, g_deg_t);
    cudaGetSymbolAddress((void**)&p_off_t, g_off_t);
    cudaGetSymbolAddress((void**)&p_cnt_t, g_cnt_t);
    cudaGetSymbolAddress((void**)&p_deg_u, g_deg_u);
    cudaGetSymbolAddress((void**)&p_off_u, g_off_u);
    cudaGetSymbolAddress((void**)&p_cnt_u, g_cnt_u);
    cudaGetSymbolAddress((void**)&p_csr_t, g_csr_t);
    cudaGetSymbolAddress((void**)&p_csr_u, g_csr_u);
    cudaGetSymbolAddress((void**)&p_sums_t, g_sums_t);
    cudaGetSymbolAddress((void**)&p_sums_u, g_sums_u);

    // lazy host-handle init (host objects only; first call is the non-captured
    // correctness run, so creation never happens inside graph capture)
    static cudaStream_t s2 = nullptr;
    static cudaEvent_t ev0 = nullptr, evH = nullptr, evP = nullptr,
                       evHS = nullptr, evT = nullptr;
    if (s2 == nullptr) {
        cudaStreamCreateWithFlags(&s2, cudaStreamNonBlocking);
        cudaEventCreateWithFlags(&ev0, cudaEventDisableTiming);
        cudaEventCreateWithFlags(&evH, cudaEventDisableTiming);
        cudaEventCreateWithFlags(&evP, cudaEventDisableTiming);
        cudaEventCreateWithFlags(&evHS, cudaEventDisableTiming);
        cudaEventCreateWithFlags(&evT, cudaEventDisableTiming);
    }

    const int nbt = (NTX + 1023) / 1024, nbu = (NUS + 1023) / 1024;
    const int nby_t = (NTX + 255) / 256, nby_u = (NUS + 255) / 256;

    // fork
    cudaEventRecord(ev0, 0);
    cudaStreamWaitEvent(s2, ev0, 0);

    // ---- NULL stream: CSR chain start ---- (launches 1-3)
    kzero<<<(NTX + 255) / 256, 256>>>(p_deg_t, NTX, p_cnt_t, NTX, p_deg_u, NUS, p_cnt_u, NUS);
    khist2<<<(2 * E + 255) / 256, 256>>>(ei_u2t, ei_t2u, p_deg_t, p_deg_u, E);
    kscan1m<<<nbt + nbu, 1024>>>(p_deg_t, p_off_t, p_sums_t, NTX,
                                 p_deg_u, p_off_u, p_sums_u, NUS, nbt);
    // ---- s2 head: fused projections (launch 4 = profiled) ----
    sgemm_dual<<<dim3(1, nby_t + nby_u, 1), 256, 0, s2>>>(
        x_tx, Wp_tx, bp_tx, p_h_tx, NTX, 128,
        x_us, Wp_us, bp_us, p_h_us, NUS, 64, nby_t);
    cudaEventRecord(evH, s2);
    // ---- NULL stream: finish CSR ----
    kscan2m<<<2, 1024>>>(p_sums_t, nbt, p_sums_u, nbu);
    kscan3m<<<nbt + nbu, 1024>>>(p_off_t, p_sums_t, NTX, p_off_u, p_sums_u, NUS, nbt);
    kscatter2<<<(2 * E + 255) / 256, 256>>>(ei_u2t, ei_t2u, p_off_t, p_cnt_t, p_csr_t,
                                            p_off_u, p_cnt_u, p_csr_u, E);
    // ---- s2: attention scalars (concurrent with NULL's hs GEMM) ----
    kvadAll5<<<5, 256, 0, s2>>>(W1_u2t, as1_u2t, ad1_u2t, W1_t2u, as1_t2u, ad1_t2u,
                                W2_u2t, ad2_u2t,
                                p_vas_u2t, p_vad_u2t, p_vas_t2u, p_vad_t2u, p_vad2);
    kdot2vF<<<(NTX + NUS + 7) / 8, 256, 0, s2>>>(
        p_h_tx, p_vad_u2t, p_vas_t2u, p_ald_u2t, p_als_t2u, NTX,
        p_h_us, p_vas_u2t, p_vad_t2u, p_als_u2t, p_ald_t2u, NUS);
    cudaEventRecord(evP, s2);
    // ---- NULL: hs_u2t = h_us @ W1_u2t (overlaps s2's kvad/kdot) ----
    cudaStreamWaitEvent(0, evH, 0);
    sgemm256<<<dim3(1, nby_u, 4), 256>>>(p_h_us, W1_u2t, nullptr, p_hs_u2t,
                                         NUS, 64, 64, 64, 256, 256, 0, 0);
    cudaEventRecord(evHS, 0);

    // ---- branch T (s2): aggh -> ald2 only (t1 never materialized) ----
    cudaStreamWaitEvent(s2, evHS, 0);
    kgat_aggh<<<(NTX + 7) / 8, 256, 0, s2>>>(p_off_t, p_deg_t, p_csr_t, p_hs_u2t,
                                             p_als_u2t, p_ald_u2t, b1_u2t, p_vad2,
                                             p_ald2, NTX);
    cudaEventRecord(evT, s2);

    // ---- branch U (NULL): aggx_u -> tfm_u -> hs2 ----
    cudaStreamWaitEvent(0, evP, 0);
    kgat_aggx<<<(NUS + 7) / 8, 256>>>(p_off_u, p_deg_u, p_csr_u, p_h_tx,
                                      p_als_t2u, p_ald_t2u, p_agg_u, NUS);
    sgemm256<<<dim3(1, nby_u, 4), 256>>>(p_agg_u, W1_t2u, b1_t2u, p_u1,
                                         NUS, 64, 64, 256, 256, 256, 1, 64);
    sgemm256<<<dim3(1, nby_u, 1), 256>>>(p_u1, W2_u2t, nullptr, p_hs2,
                                         NUS, 32, 256, 256, 32, 32, 0, 0);

    // ---- join + final (NULL): kgat2 with fused inline als2 ----
    cudaStreamWaitEvent(0, evT, 0);
    kgat2<<<(NTX + 7) / 8, 256>>>(p_off_t, p_deg_t, p_csr_t, p_hs2, as2_u2t, p_ald2,
                                  b2_u2t, Wc, bc, (float*)d_out, NTX);
}